// round 13
// baseline (speedup 1.0000x reference)
#include <cuda_runtime.h>
#include <float.h>
#include <math.h>
#include <stdint.h>

#define BB 16
#define NP 1024
#define KNN 20
#define EDGES (BB*NP*KNN)

// ---------------- scratch ----------------
__device__ float g_uv[BB*NP*2048];        // [u | v], stride 2*cout
__device__ float g_u[BB*NP*128];          // u + max_k v (layers 1-3, cout<=128)
__device__ float g_ah[BB*NP*128];         // A hi plane [M][Kp]
__device__ float g_al[BB*NP*128];         // A lo plane
__device__ float g_wh[294912];            // W hi planes, all 4 layers at offsets
__device__ float g_wl[294912];
__device__ float g_sq[BB*NP];
__device__ int   g_idx[BB*NP*KNN];
__device__ float g_sum[1024];             // zero at load; k_fin re-zeros each layer
__device__ float g_sum2[1024];
__device__ float g_scale[1024];
__device__ float g_shift[1024];
__device__ int   g_pool[BB*1024];         // encoded raw max, then float after k_pfin
__device__ float g_fc1[BB*512];

__device__ __forceinline__ float f2tf32f(float f) {
    unsigned r;
    asm("cvt.rna.tf32.f32 %0, %1;" : "=r"(r) : "f"(f));
    return __uint_as_float(r);
}

// order-preserving float<->int (handles negatives) for atomicMax
__device__ __forceinline__ int encf(float f) {
    int i = __float_as_int(f);
    return i >= 0 ? i : (i ^ 0x7fffffff);
}
__device__ __forceinline__ float decf(int i) {
    return __int_as_float(i >= 0 ? i : (i ^ 0x7fffffff));
}
__device__ __forceinline__ unsigned ordkey(float f) {
    unsigned u = __float_as_uint(f);
    return (u & 0x80000000u) ? ~u : (u | 0x80000000u);
}

// cp.async helpers
__device__ __forceinline__ void cp16(uint32_t dst, const void* src) {
    asm volatile("cp.async.ca.shared.global [%0], [%1], 16;\n" :: "r"(dst), "l"(src));
}
__device__ __forceinline__ void cp_commit() { asm volatile("cp.async.commit_group;\n"); }
__device__ __forceinline__ void cp_wait1() { asm volatile("cp.async.wait_group 1;\n"); }
__device__ __forceinline__ void cp_wait0() { asm volatile("cp.async.wait_group 0;\n"); }

#define MMA3(ACC, AH, AL, BH, BL)                                                \
    do {                                                                         \
        asm volatile("mma.sync.aligned.m16n8k8.row.col.f32.tf32.tf32.f32 "       \
            "{%0,%1,%2,%3}, {%4,%5,%6,%7}, {%8,%9}, {%0,%1,%2,%3};"              \
            : "+f"(ACC[0]), "+f"(ACC[1]), "+f"(ACC[2]), "+f"(ACC[3])             \
            : "r"(AH[0]), "r"(AH[1]), "r"(AH[2]), "r"(AH[3]), "r"(BL[0]), "r"(BL[1])); \
        asm volatile("mma.sync.aligned.m16n8k8.row.col.f32.tf32.tf32.f32 "       \
            "{%0,%1,%2,%3}, {%4,%5,%6,%7}, {%8,%9}, {%0,%1,%2,%3};"              \
            : "+f"(ACC[0]), "+f"(ACC[1]), "+f"(ACC[2]), "+f"(ACC[3])             \
            : "r"(AL[0]), "r"(AL[1]), "r"(AL[2]), "r"(AL[3]), "r"(BH[0]), "r"(BH[1])); \
        asm volatile("mma.sync.aligned.m16n8k8.row.col.f32.tf32.tf32.f32 "       \
            "{%0,%1,%2,%3}, {%4,%5,%6,%7}, {%8,%9}, {%0,%1,%2,%3};"              \
            : "+f"(ACC[0]), "+f"(ACC[1]), "+f"(ACC[2]), "+f"(ACC[3])             \
            : "r"(AH[0]), "r"(AH[1]), "r"(AH[2]), "r"(AH[3]), "r"(BH[0]), "r"(BH[1])); \
    } while (0)

// ---------------- split layer-1 input (pos) into planes + squared norms ----------------
__global__ void k_splitA(const float* x, int K, int Kp) {
    int m = blockIdx.x * 256 + threadIdx.x;
    if (m >= BB * NP) return;
    float s = 0.f;
    for (int k = 0; k < Kp; k++) {
        float v = (k < K) ? x[(size_t)m * K + k] : 0.f;
        float h = f2tf32f(v);
        g_ah[(size_t)m * Kp + k] = h;
        g_al[(size_t)m * Kp + k] = f2tf32f(v - h);
        s += v * v;
    }
    g_sq[m] = s;
}

// ---------------- fused Gram + top-20, register-resident selection ----------------
#define GBK 16
#define P_STR 20
#define P_BUF (128*P_STR)
#define DS 129
#define GRAMK_SMEM ((8*P_BUF + 128*DS) * 4)   // 147968 B

__global__ __launch_bounds__(256) void k_gramk(int Kp) {
    extern __shared__ float smem[];
    float* MH = smem;
    float* ML = MH + 2 * P_BUF;
    float* NH = ML + 2 * P_BUF;
    float* NL = NH + 2 * P_BUF;
    float* D  = NL + 2 * P_BUF;          // [128][DS]

    uint32_t mh0 = (uint32_t)__cvta_generic_to_shared(MH);
    uint32_t ml0 = (uint32_t)__cvta_generic_to_shared(ML);
    uint32_t nh0 = (uint32_t)__cvta_generic_to_shared(NH);
    uint32_t nl0 = (uint32_t)__cvta_generic_to_shared(NL);

    int b = blockIdx.z;
    int mt = blockIdx.x;
    int M0 = b * NP + mt * 128;

    int tid = threadIdx.x;
    int wid = tid >> 5, lane = tid & 31;
    int wm = wid >> 2, wn = wid & 3;
    int gid = lane >> 2, tig = lane & 3;

    int N0 = b * NP;

    auto prefetch = [&](int buf, int k0) {
        #pragma unroll
        for (int i = 0; i < 2; i++) {
            int e = i * 256 + tid;
            int m = e >> 2, kq = e & 3;
            uint32_t d = (uint32_t)((buf * P_BUF + m * P_STR + kq * 4) * 4);
            size_t srm = (size_t)(M0 + m) * Kp + k0 + kq * 4;
            size_t srn = (size_t)(N0 + m) * Kp + k0 + kq * 4;
            cp16(mh0 + d, &g_ah[srm]);
            cp16(ml0 + d, &g_al[srm]);
            cp16(nh0 + d, &g_ah[srn]);
            cp16(nl0 + d, &g_al[srn]);
        }
        cp_commit();
    };

    // register-resident top-20 (compile-time indexed ONLY)
    unsigned long long list[KNN];
    #pragma unroll
    for (int t = 0; t < KNN; t++) list[t] = 0xFFFFFFFFFFFFFFFFull;
    unsigned long long curmax = 0xFFFFFFFFFFFFFFFFull;
    int maxpos = 0;
    int row = tid;
    int KT = Kp / GBK;

    for (int nt = 0; nt < 8; nt++) {
        N0 = b * NP + nt * 128;

        float acc[4][4][4];
        #pragma unroll
        for (int mi = 0; mi < 4; mi++)
            #pragma unroll
            for (int ni = 0; ni < 4; ni++)
                #pragma unroll
                for (int r = 0; r < 4; r++) acc[mi][ni][r] = 0.f;

        prefetch(0, 0);
        int cur = 0;
        for (int kt = 0; kt < KT; kt++) {
            bool has_next = (kt + 1 < KT);
            if (has_next) prefetch(cur ^ 1, (kt + 1) * GBK);
            if (has_next) cp_wait1(); else cp_wait0();
            __syncthreads();

            const float* mh = MH + cur * P_BUF;
            const float* ml = ML + cur * P_BUF;
            const float* nh = NH + cur * P_BUF;
            const float* nl = NL + cur * P_BUF;

            #pragma unroll
            for (int kk = 0; kk < GBK; kk += 8) {
                unsigned bfH[4][2], bfL[4][2];
                #pragma unroll
                for (int ni = 0; ni < 4; ni++) {
                    int cb = wn * 32 + ni * 8 + gid;
                    bfH[ni][0] = __float_as_uint(nh[cb * P_STR + kk + tig]);
                    bfH[ni][1] = __float_as_uint(nh[cb * P_STR + kk + tig + 4]);
                    bfL[ni][0] = __float_as_uint(nl[cb * P_STR + kk + tig]);
                    bfL[ni][1] = __float_as_uint(nl[cb * P_STR + kk + tig + 4]);
                }
                #pragma unroll
                for (int mi = 0; mi < 4; mi++) {
                    int rb = wm * 64 + mi * 16;
                    unsigned aH[4], aL[4];
                    aH[0] = __float_as_uint(mh[(rb + gid) * P_STR + kk + tig]);
                    aH[1] = __float_as_uint(mh[(rb + gid + 8) * P_STR + kk + tig]);
                    aH[2] = __float_as_uint(mh[(rb + gid) * P_STR + kk + tig + 4]);
                    aH[3] = __float_as_uint(mh[(rb + gid + 8) * P_STR + kk + tig + 4]);
                    aL[0] = __float_as_uint(ml[(rb + gid) * P_STR + kk + tig]);
                    aL[1] = __float_as_uint(ml[(rb + gid + 8) * P_STR + kk + tig]);
                    aL[2] = __float_as_uint(ml[(rb + gid) * P_STR + kk + tig + 4]);
                    aL[3] = __float_as_uint(ml[(rb + gid + 8) * P_STR + kk + tig + 4]);
                    #pragma unroll
                    for (int ni = 0; ni < 4; ni++)
                        MMA3(acc[mi][ni], aH, aL, bfH[ni], bfL[ni]);
                }
            }
            __syncthreads();
            cur ^= 1;
        }

        // epilogue: distances into smem D
        #pragma unroll
        for (int mi = 0; mi < 4; mi++) {
            int rl0 = wm * 64 + mi * 16 + gid;
            float sr0 = g_sq[M0 + rl0], sr1 = g_sq[M0 + rl0 + 8];
            #pragma unroll
            for (int ni = 0; ni < 4; ni++) {
                int cl = wn * 32 + ni * 8 + tig * 2;
                float sc0 = g_sq[N0 + cl], sc1 = g_sq[N0 + cl + 1];
                float d00 = sr0 + sc0 - 2.f * acc[mi][ni][0];
                float d01 = sr0 + sc1 - 2.f * acc[mi][ni][1];
                float d10 = sr1 + sc0 - 2.f * acc[mi][ni][2];
                float d11 = sr1 + sc1 - 2.f * acc[mi][ni][3];
                if (nt == mt) {
                    if (rl0 == cl)         d00 += 1e10f;
                    if (rl0 == cl + 1)     d01 += 1e10f;
                    if (rl0 + 8 == cl)     d10 += 1e10f;
                    if (rl0 + 8 == cl + 1) d11 += 1e10f;
                }
                D[rl0 * DS + cl]           = d00;
                D[rl0 * DS + cl + 1]       = d01;
                D[(rl0 + 8) * DS + cl]     = d10;
                D[(rl0 + 8) * DS + cl + 1] = d11;
            }
        }
        __syncthreads();

        // selection: one thread per row; compile-time indexed insert/rescan
        if (tid < 128) {
            unsigned base = (unsigned)(nt * 128);
            for (int c = 0; c < 128; c++) {
                unsigned long long key =
                    ((unsigned long long)ordkey(D[row * DS + c]) << 32) | (base + c);
                if (key < curmax) {
                    #pragma unroll
                    for (int j = 0; j < KNN; j++)
                        if (j == maxpos) list[j] = key;
                    curmax = list[0]; maxpos = 0;
                    #pragma unroll
                    for (int j = 1; j < KNN; j++)
                        if (list[j] > curmax) { curmax = list[j]; maxpos = j; }
                }
            }
        }
        __syncthreads();
    }

    if (tid < 128) {
        #pragma unroll
        for (int t = 0; t < KNN; t++)
            g_idx[(size_t)(M0 + row) * KNN + t] = (int)(list[t] & 0xFFFFFFFFull);
    }
}

// ---------------- split W into tf32 hi/lo planes (per-layer offset) ----------------
__global__ void k_splitW(const float* W, int K, int Kp, int cout, int woff) {
    int i = blockIdx.x * 256 + threadIdx.x;
    int N = 2 * cout;
    if (i >= Kp * N) return;
    int k = i / N, col = i % N;
    float v = 0.f;
    if (k < K) {
        if (col < cout) v = W[(size_t)k * cout + col];
        else {
            int c2 = col - cout;
            v = W[(size_t)(K + k) * cout + c2] - W[(size_t)k * cout + c2];
        }
    }
    float h = f2tf32f(v);
    g_wh[woff + i] = h;
    g_wl[woff + i] = f2tf32f(v - h);
}

// ---------------- 3xTF32 GEMM, pre-split operands, cp.async double-buffered ----------------
#define A_STR 20
#define B_STR 136
#define A_BUF (128*A_STR)
#define B_BUF (GBK*B_STR)
#define GEMM_SMEM ((2*A_BUF*2 + 2*B_BUF*2) * 4)   // 75776 bytes

__global__ __launch_bounds__(256) void k_gemm_tc(int M, int Kp, int N, int woff) {
    extern __shared__ float smem[];
    float* AsH = smem;
    float* AsL = AsH + 2 * A_BUF;
    float* BsH = AsL + 2 * A_BUF;
    float* BsL = BsH + 2 * B_BUF;

    uint32_t aH0 = (uint32_t)__cvta_generic_to_shared(AsH);
    uint32_t aL0 = (uint32_t)__cvta_generic_to_shared(AsL);
    uint32_t bH0 = (uint32_t)__cvta_generic_to_shared(BsH);
    uint32_t bL0 = (uint32_t)__cvta_generic_to_shared(BsL);

    int tid = threadIdx.x;
    int m0 = blockIdx.y * 128, n0 = blockIdx.x * 128;
    int wid = tid >> 5, lane = tid & 31;
    int wm = wid >> 2, wn = wid & 3;
    int gid = lane >> 2, tig = lane & 3;

    float acc[4][4][4];
    #pragma unroll
    for (int mi = 0; mi < 4; mi++)
        #pragma unroll
        for (int ni = 0; ni < 4; ni++)
            #pragma unroll
            for (int r = 0; r < 4; r++) acc[mi][ni][r] = 0.f;

    auto prefetch = [&](int buf, int k0) {
        #pragma unroll
        for (int i = 0; i < 2; i++) {
            int e = i * 256 + tid;
            int m = e >> 2, kq = e & 3;
            size_t src = (size_t)(m0 + m) * Kp + k0 + kq * 4;
            uint32_t d = (uint32_t)((buf * A_BUF + m * A_STR + kq * 4) * 4);
            cp16(aH0 + d, &g_ah[src]);
            cp16(aL0 + d, &g_al[src]);
        }
        #pragma unroll
        for (int i = 0; i < 2; i++) {
            int e = i * 256 + tid;
            int k = e >> 5, nq = e & 31;
            size_t src = (size_t)woff + (size_t)(k0 + k) * N + n0 + nq * 4;
            uint32_t d = (uint32_t)((buf * B_BUF + k * B_STR + nq * 4) * 4);
            cp16(bH0 + d, &g_wh[src]);
            cp16(bL0 + d, &g_wl[src]);
        }
        cp_commit();
    };

    int KT = Kp / GBK;
    prefetch(0, 0);

    int cur = 0;
    for (int kt = 0; kt < KT; kt++) {
        bool has_next = (kt + 1 < KT);
        if (has_next) prefetch(cur ^ 1, (kt + 1) * GBK);
        if (has_next) cp_wait1(); else cp_wait0();
        __syncthreads();

        const float* aH = AsH + cur * A_BUF;
        const float* aL = AsL + cur * A_BUF;
        const float* bH = BsH + cur * B_BUF;
        const float* bL = BsL + cur * B_BUF;

        #pragma unroll
        for (int kk = 0; kk < GBK; kk += 8) {
            unsigned bfH[4][2], bfL[4][2];
            #pragma unroll
            for (int ni = 0; ni < 4; ni++) {
                int cb = wn * 32 + ni * 8;
                bfH[ni][0] = __float_as_uint(bH[(kk + tig) * B_STR + cb + gid]);
                bfH[ni][1] = __float_as_uint(bH[(kk + tig + 4) * B_STR + cb + gid]);
                bfL[ni][0] = __float_as_uint(bL[(kk + tig) * B_STR + cb + gid]);
                bfL[ni][1] = __float_as_uint(bL[(kk + tig + 4) * B_STR + cb + gid]);
            }
            #pragma unroll
            for (int mi = 0; mi < 4; mi++) {
                int rb = wm * 64 + mi * 16;
                unsigned aHf[4], aLf[4];
                aHf[0] = __float_as_uint(aH[(rb + gid) * A_STR + kk + tig]);
                aHf[1] = __float_as_uint(aH[(rb + gid + 8) * A_STR + kk + tig]);
                aHf[2] = __float_as_uint(aH[(rb + gid) * A_STR + kk + tig + 4]);
                aHf[3] = __float_as_uint(aH[(rb + gid + 8) * A_STR + kk + tig + 4]);
                aLf[0] = __float_as_uint(aL[(rb + gid) * A_STR + kk + tig]);
                aLf[1] = __float_as_uint(aL[(rb + gid + 8) * A_STR + kk + tig]);
                aLf[2] = __float_as_uint(aL[(rb + gid) * A_STR + kk + tig + 4]);
                aLf[3] = __float_as_uint(aL[(rb + gid + 8) * A_STR + kk + tig + 4]);
                #pragma unroll
                for (int ni = 0; ni < 4; ni++)
                    MMA3(acc[mi][ni], aHf, aLf, bfH[ni], bfL[ni]);
            }
        }
        __syncthreads();
        cur ^= 1;
    }

    #pragma unroll
    for (int mi = 0; mi < 4; mi++) {
        int row0 = m0 + wm * 64 + mi * 16 + gid;
        #pragma unroll
        for (int ni = 0; ni < 4; ni++) {
            int col = n0 + wn * 32 + ni * 8 + tig * 2;
            *(float2*)&g_uv[(size_t)row0 * N + col]       = make_float2(acc[mi][ni][0], acc[mi][ni][1]);
            *(float2*)&g_uv[(size_t)(row0 + 8) * N + col] = make_float2(acc[mi][ni][2], acc[mi][ni][3]);
        }
    }
}

// ---------------- gather over k : max + stats; layer 4 fuses global pool ----------------
#define PTS 16
__global__ __launch_bounds__(256) void k_edge(int cout, int dopool) {
    __shared__ float ssum[1024], ssum2[1024];
    int tid = threadIdx.x;
    for (int i = tid; i < cout; i += 256) { ssum[i] = 0.f; ssum2[i] = 0.f; }
    __syncthreads();

    int cpg = cout >> 2;
    int pp  = 256 / cpg;
    int pi = tid / cpg, ci = tid % cpg;
    int base = blockIdx.x * PTS;
    int b = base / NP;
    int C2 = 2 * cout;
    int o = ci * 4;

    float4 se  = make_float4(0.f, 0.f, 0.f, 0.f);
    float4 se2 = make_float4(0.f, 0.f, 0.f, 0.f);
    float4 pm  = make_float4(-FLT_MAX, -FLT_MAX, -FLT_MAX, -FLT_MAX);

    for (int p0 = 0; p0 < PTS; p0 += pp) {
        int bn = base + p0 + pi;
        const int* idxp = g_idx + (size_t)bn * KNN;
        int jj[KNN];
        #pragma unroll
        for (int k = 0; k < KNN; k++) jj[k] = __ldg(&idxp[k]);

        float4 u = *(const float4*)&g_uv[(size_t)bn * C2 + o];
        float4 mv = make_float4(-FLT_MAX, -FLT_MAX, -FLT_MAX, -FLT_MAX);
        #pragma unroll
        for (int k = 0; k < KNN; k++) {
            float4 v = *(const float4*)&g_uv[((size_t)b * NP + jj[k]) * C2 + cout + o];
            mv.x = fmaxf(mv.x, v.x); mv.y = fmaxf(mv.y, v.y);
            mv.z = fmaxf(mv.z, v.z); mv.w = fmaxf(mv.w, v.w);
            float4 e = make_float4(u.x + v.x, u.y + v.y, u.z + v.z, u.w + v.w);
            se.x += e.x; se.y += e.y; se.z += e.z; se.w += e.w;
            se2.x += e.x * e.x; se2.y += e.y * e.y; se2.z += e.z * e.z; se2.w += e.w * e.w;
        }
        float4 tot = make_float4(u.x + mv.x, u.y + mv.y, u.z + mv.z, u.w + mv.w);
        if (!dopool) {
            *(float4*)&g_u[(size_t)bn * cout + o] = tot;
        } else {
            pm.x = fmaxf(pm.x, tot.x); pm.y = fmaxf(pm.y, tot.y);
            pm.z = fmaxf(pm.z, tot.z); pm.w = fmaxf(pm.w, tot.w);
        }
    }

    if (dopool) {
        int* dst = &g_pool[b * 1024 + o];
        atomicMax(dst + 0, encf(pm.x));
        atomicMax(dst + 1, encf(pm.y));
        atomicMax(dst + 2, encf(pm.z));
        atomicMax(dst + 3, encf(pm.w));
    }

    atomicAdd(&ssum[o + 0], se.x);  atomicAdd(&ssum[o + 1], se.y);
    atomicAdd(&ssum[o + 2], se.z);  atomicAdd(&ssum[o + 3], se.w);
    atomicAdd(&ssum2[o + 0], se2.x); atomicAdd(&ssum2[o + 1], se2.y);
    atomicAdd(&ssum2[o + 2], se2.z); atomicAdd(&ssum2[o + 3], se2.w);
    __syncthreads();
    for (int i = tid; i < cout; i += 256) {
        atomicAdd(&g_sum[i],  ssum[i]);
        atomicAdd(&g_sum2[i], ssum2[i]);
    }
}

// ---------------- BN finalize (+ re-zero accumulators) ----------------
__global__ void k_fin(const float* gam, const float* bet, int cout) {
    int o = blockIdx.x * 256 + threadIdx.x;
    float s_ = g_sum[o], s2_ = g_sum2[o];
    g_sum[o] = 0.f;  g_sum2[o] = 0.f;
    if (o >= cout) return;
    float inv = 1.f / (float)EDGES;
    float mean = s_ * inv;
    float var  = s2_ * inv - mean * mean;
    float s = rsqrtf(var + 1e-5f) * gam[o];
    g_scale[o] = s;
    g_shift[o] = bet[o] - mean * s;
}

// ---------------- apply BN + relu, write next-layer planes + squared norms ----------------
__global__ void k_apply(int cout) {
    __shared__ float ssq[16];
    int tid = threadIdx.x;
    int ppb = 1024 / cout;
    if (tid < ppb) ssq[tid] = 0.f;
    __syncthreads();

    int i4 = (blockIdx.x * 256 + tid) * 4;
    int o = i4 & (cout - 1);
    int pl = tid / (cout >> 2);
    float4 u = *(const float4*)&g_u[i4];
    float4 s = *(const float4*)&g_scale[o];
    float4 t = *(const float4*)&g_shift[o];
    float4 v, h, l;
    v.x = fmaxf(u.x * s.x + t.x, 0.f);
    v.y = fmaxf(u.y * s.y + t.y, 0.f);
    v.z = fmaxf(u.z * s.z + t.z, 0.f);
    v.w = fmaxf(u.w * s.w + t.w, 0.f);
    h.x = f2tf32f(v.x); h.y = f2tf32f(v.y); h.z = f2tf32f(v.z); h.w = f2tf32f(v.w);
    l.x = f2tf32f(v.x - h.x); l.y = f2tf32f(v.y - h.y);
    l.z = f2tf32f(v.z - h.z); l.w = f2tf32f(v.w - h.w);
    *(float4*)&g_ah[i4] = h;
    *(float4*)&g_al[i4] = l;

    atomicAdd(&ssq[pl], v.x * v.x + v.y * v.y + v.z * v.z + v.w * v.w);
    __syncthreads();
    if (tid < ppb) g_sq[blockIdx.x * ppb + tid] = ssq[tid];
}

// ---------------- pool init (encoded -inf) + pooled BN finalize ----------------
__global__ void k_pzero() {
    int i = blockIdx.x * 256 + threadIdx.x;
    if (i < BB * 1024) g_pool[i] = (int)0x80000000;
}

__global__ void k_pfin() {
    int i = blockIdx.x * 256 + threadIdx.x;
    int o = i & 1023;
    float m = decf(g_pool[i]);
    float v = fmaxf(g_scale[o] * m + g_shift[o], 0.f);
    ((float*)g_pool)[i] = v;
}

// ---------------- FC layers ----------------
__global__ void k_fc1(const float* W, const float* bias) {
    int b = blockIdx.x, t = threadIdx.x;
    float a0 = bias[t], a1 = bias[t + 256];
    const float* y = (const float*)g_pool + b * 1024;
    #pragma unroll 4
    for (int c = 0; c < 1024; c++) {
        float xv = y[c];
        a0 += xv * W[c * 512 + t];
        a1 += xv * W[c * 512 + t + 256];
    }
    g_fc1[b * 512 + t]       = fmaxf(a0, 0.f);
    g_fc1[b * 512 + t + 256] = fmaxf(a1, 0.f);
}

__global__ void k_fc2(const float* W, const float* bias, float* out) {
    int b = blockIdx.x, o = threadIdx.x;
    if (o >= 40) return;
    float a = bias[o];
    const float* y = g_fc1 + b * 512;
    #pragma unroll 4
    for (int c = 0; c < 512; c++) a += y[c] * W[c * 40 + o];
    out[b * 40 + o] = a;
}

// ---------------- launcher (fork/join overlap; weights pre-split on s2) ----------------
extern "C" void kernel_launch(void* const* d_in, const int* in_sizes, int n_in,
                              void* d_out, int out_size) {
    (void)in_sizes; (void)n_in; (void)out_size;
    const float* pos = (const float*)d_in[0];
    const float* W[4]  = {(const float*)d_in[1],  (const float*)d_in[5],
                          (const float*)d_in[9],  (const float*)d_in[13]};
    const float* gm[4] = {(const float*)d_in[3],  (const float*)d_in[7],
                          (const float*)d_in[11], (const float*)d_in[15]};
    const float* bt[4] = {(const float*)d_in[4],  (const float*)d_in[8],
                          (const float*)d_in[12], (const float*)d_in[16]};
    const float* Wc1 = (const float*)d_in[17];
    const float* bc1 = (const float*)d_in[18];
    const float* Wc2 = (const float*)d_in[19];
    const float* bc2 = (const float*)d_in[20];

    const int cin[4]  = {3, 64, 64, 128};
    const int Kp[4]   = {16, 64, 64, 128};
    const int cout[4] = {64, 64, 128, 1024};
    const int woff[4] = {0, 2048, 10240, 26624};
    const int M = BB * NP;

    static cudaStream_t s2 = nullptr;
    static cudaEvent_t ev0, evF[4], evJ[4];
    if (!s2) {
        cudaStreamCreateWithFlags(&s2, cudaStreamNonBlocking);
        cudaEventCreateWithFlags(&ev0, cudaEventDisableTiming);
        for (int i = 0; i < 4; i++) {
            cudaEventCreateWithFlags(&evF[i], cudaEventDisableTiming);
            cudaEventCreateWithFlags(&evJ[i], cudaEventDisableTiming);
        }
        cudaFuncSetAttribute(k_gemm_tc, cudaFuncAttributeMaxDynamicSharedMemorySize, GEMM_SMEM);
        cudaFuncSetAttribute(k_gramk,  cudaFuncAttributeMaxDynamicSharedMemorySize, GRAMK_SMEM);
    }

    k_pzero<<<64, 256>>>();
    // fork s2 and run all weight splits upfront (independent of activations)
    cudaEventRecord(ev0, 0);
    cudaStreamWaitEvent(s2, ev0, 0);
    for (int l = 0; l < 4; l++)
        k_splitW<<<(Kp[l] * 2 * cout[l] + 255) / 256, 256, 0, s2>>>(
            W[l], cin[l], Kp[l], cout[l], woff[l]);

    for (int l = 0; l < 4; l++) {
        int N2 = 2 * cout[l];
        if (l == 0) k_splitA<<<64, 256>>>(pos, cin[0], Kp[0]);

        // fork: activation planes ready -> gemm on s2
        cudaEventRecord(evF[l], 0);
        cudaStreamWaitEvent(s2, evF[l], 0);
        k_gemm_tc<<<dim3(N2 / 128, M / 128), 256, GEMM_SMEM, s2>>>(M, Kp[l], N2, woff[l]);
        cudaEventRecord(evJ[l], s2);

        // main: fused gram + top-20 (register-resident selection)
        k_gramk<<<dim3(8, 1, BB), 256, GRAMK_SMEM>>>(Kp[l]);

        // join: edge needs gemm output + knn indices
        cudaStreamWaitEvent(0, evJ[l], 0);
        k_edge<<<M / PTS, 256>>>(cout[l], l == 3 ? 1 : 0);
        k_fin<<<4, 256>>>(gm[l], bt[l], cout[l]);
        if (l < 3) k_apply<<<(M * cout[l]) / 1024, 256>>>(cout[l]);
        else       k_pfin<<<64, 256>>>();
    }
    k_fc1<<<BB, 256>>>(Wc1, bc1);
    k_fc2<<<BB, 64>>>(Wc2, bc2, (float*)d_out);
}

// round 14
// speedup vs baseline: 2.0969x; 2.0969x over previous
#include <cuda_runtime.h>
#include <float.h>
#include <math.h>
#include <stdint.h>

#define BB 16
#define NP 1024
#define KNN 20
#define EDGES (BB*NP*KNN)

// ---------------- scratch ----------------
__device__ float g_gram[BB*NP*NP];
__device__ float g_uv[BB*NP*2048];        // [u | v], stride 2*cout
__device__ float g_u[BB*NP*1024];         // u + max_k v  (layers 1-3)
__device__ float g_ah[BB*NP*128];         // A hi plane [M][Kp]
__device__ float g_al[BB*NP*128];         // A lo plane
__device__ float g_wh[128*2048];          // W hi plane [Kp][N] (per layer)
__device__ float g_wl[128*2048];
__device__ float g_sq[BB*NP];
__device__ int   g_idx[BB*NP*KNN];
__device__ float g_sum[1024];             // zero at load; k_fin re-zeros each layer
__device__ float g_sum2[1024];
__device__ float g_scale[1024];
__device__ float g_shift[1024];
__device__ int   g_pool[BB*1024];         // encoded raw max, then float after k_pfin
__device__ float g_fc1[BB*512];

__device__ __forceinline__ float f2tf32f(float f) {
    unsigned r;
    asm("cvt.rna.tf32.f32 %0, %1;" : "=r"(r) : "f"(f));
    return __uint_as_float(r);
}

__device__ __forceinline__ int encf(float f) {
    int i = __float_as_int(f);
    return i >= 0 ? i : (i ^ 0x7fffffff);
}
__device__ __forceinline__ float decf(int i) {
    return __int_as_float(i >= 0 ? i : (i ^ 0x7fffffff));
}
__device__ __forceinline__ unsigned ordkey(float f) {
    unsigned u = __float_as_uint(f);
    return (u & 0x80000000u) ? ~u : (u | 0x80000000u);
}

// cp.async helpers
__device__ __forceinline__ void cp16(uint32_t dst, const void* src) {
    asm volatile("cp.async.ca.shared.global [%0], [%1], 16;\n" :: "r"(dst), "l"(src));
}
__device__ __forceinline__ void cp_commit() { asm volatile("cp.async.commit_group;\n"); }
__device__ __forceinline__ void cp_wait1() { asm volatile("cp.async.wait_group 1;\n"); }
__device__ __forceinline__ void cp_wait0() { asm volatile("cp.async.wait_group 0;\n"); }

#define MMA3(ACC, AH, AL, BH, BL)                                                \
    do {                                                                         \
        asm volatile("mma.sync.aligned.m16n8k8.row.col.f32.tf32.tf32.f32 "       \
            "{%0,%1,%2,%3}, {%4,%5,%6,%7}, {%8,%9}, {%0,%1,%2,%3};"              \
            : "+f"(ACC[0]), "+f"(ACC[1]), "+f"(ACC[2]), "+f"(ACC[3])             \
            : "r"(AH[0]), "r"(AH[1]), "r"(AH[2]), "r"(AH[3]), "r"(BL[0]), "r"(BL[1])); \
        asm volatile("mma.sync.aligned.m16n8k8.row.col.f32.tf32.tf32.f32 "       \
            "{%0,%1,%2,%3}, {%4,%5,%6,%7}, {%8,%9}, {%0,%1,%2,%3};"              \
            : "+f"(ACC[0]), "+f"(ACC[1]), "+f"(ACC[2]), "+f"(ACC[3])             \
            : "r"(AL[0]), "r"(AL[1]), "r"(AL[2]), "r"(AL[3]), "r"(BH[0]), "r"(BH[1])); \
        asm volatile("mma.sync.aligned.m16n8k8.row.col.f32.tf32.tf32.f32 "       \
            "{%0,%1,%2,%3}, {%4,%5,%6,%7}, {%8,%9}, {%0,%1,%2,%3};"              \
            : "+f"(ACC[0]), "+f"(ACC[1]), "+f"(ACC[2]), "+f"(ACC[3])             \
            : "r"(AH[0]), "r"(AH[1]), "r"(AH[2]), "r"(AH[3]), "r"(BH[0]), "r"(BH[1])); \
    } while (0)

// ---------------- split layer-1 input (pos) into planes + squared norms ----------------
__global__ void k_splitA(const float* x, int K, int Kp) {
    int m = blockIdx.x * 256 + threadIdx.x;
    if (m >= BB * NP) return;
    float s = 0.f;
    for (int k = 0; k < Kp; k++) {
        float v = (k < K) ? x[(size_t)m * K + k] : 0.f;
        float h = f2tf32f(v);
        g_ah[(size_t)m * Kp + k] = h;
        g_al[(size_t)m * Kp + k] = f2tf32f(v - h);
        s += v * v;
    }
    g_sq[m] = s;
}

// ---------------- 3xTF32 Gram: symmetric, 36 tile pairs, tensor-core ----------------
#define GBK 16
#define P_STR 20
#define P_BUF (128*P_STR)
#define GRAM_SMEM (8 * P_BUF * 4)         // 81920 B
#define T_STR 132

__global__ __launch_bounds__(256) void k_gram_tc(int Kp) {
    extern __shared__ float smem[];
    float* MH = smem;
    float* ML = MH + 2 * P_BUF;
    float* NH = ML + 2 * P_BUF;
    float* NL = NH + 2 * P_BUF;

    uint32_t mh0 = (uint32_t)__cvta_generic_to_shared(MH);
    uint32_t ml0 = (uint32_t)__cvta_generic_to_shared(ML);
    uint32_t nh0 = (uint32_t)__cvta_generic_to_shared(NH);
    uint32_t nl0 = (uint32_t)__cvta_generic_to_shared(NL);

    int b = blockIdx.z;
    int p = blockIdx.x, mt = 0;
    while (p >= 8 - mt) { p -= 8 - mt; mt++; }
    int nt = mt + p;
    int m0 = mt * 128, n0 = nt * 128;
    int M0 = b * NP + m0, N0 = b * NP + n0;

    int tid = threadIdx.x;
    int wid = tid >> 5, lane = tid & 31;
    int wm = wid >> 2, wn = wid & 3;
    int gid = lane >> 2, tig = lane & 3;

    float acc[4][4][4];
    #pragma unroll
    for (int mi = 0; mi < 4; mi++)
        #pragma unroll
        for (int ni = 0; ni < 4; ni++)
            #pragma unroll
            for (int r = 0; r < 4; r++) acc[mi][ni][r] = 0.f;

    auto prefetch = [&](int buf, int k0) {
        #pragma unroll
        for (int i = 0; i < 2; i++) {
            int e = i * 256 + tid;
            int m = e >> 2, kq = e & 3;
            uint32_t d = (uint32_t)((buf * P_BUF + m * P_STR + kq * 4) * 4);
            size_t srm = (size_t)(M0 + m) * Kp + k0 + kq * 4;
            size_t srn = (size_t)(N0 + m) * Kp + k0 + kq * 4;
            cp16(mh0 + d, &g_ah[srm]);
            cp16(ml0 + d, &g_al[srm]);
            cp16(nh0 + d, &g_ah[srn]);
            cp16(nl0 + d, &g_al[srn]);
        }
        cp_commit();
    };

    int KT = Kp / GBK;
    prefetch(0, 0);

    int cur = 0;
    for (int kt = 0; kt < KT; kt++) {
        bool has_next = (kt + 1 < KT);
        if (has_next) prefetch(cur ^ 1, (kt + 1) * GBK);
        if (has_next) cp_wait1(); else cp_wait0();
        __syncthreads();

        const float* mh = MH + cur * P_BUF;
        const float* ml = ML + cur * P_BUF;
        const float* nh = NH + cur * P_BUF;
        const float* nl = NL + cur * P_BUF;

        #pragma unroll
        for (int kk = 0; kk < GBK; kk += 8) {
            unsigned bfH[4][2], bfL[4][2];
            #pragma unroll
            for (int ni = 0; ni < 4; ni++) {
                int cb = wn * 32 + ni * 8 + gid;
                bfH[ni][0] = __float_as_uint(nh[cb * P_STR + kk + tig]);
                bfH[ni][1] = __float_as_uint(nh[cb * P_STR + kk + tig + 4]);
                bfL[ni][0] = __float_as_uint(nl[cb * P_STR + kk + tig]);
                bfL[ni][1] = __float_as_uint(nl[cb * P_STR + kk + tig + 4]);
            }
            #pragma unroll
            for (int mi = 0; mi < 4; mi++) {
                int rb = wm * 64 + mi * 16;
                unsigned aH[4], aL[4];
                aH[0] = __float_as_uint(mh[(rb + gid) * P_STR + kk + tig]);
                aH[1] = __float_as_uint(mh[(rb + gid + 8) * P_STR + kk + tig]);
                aH[2] = __float_as_uint(mh[(rb + gid) * P_STR + kk + tig + 4]);
                aH[3] = __float_as_uint(mh[(rb + gid + 8) * P_STR + kk + tig + 4]);
                aL[0] = __float_as_uint(ml[(rb + gid) * P_STR + kk + tig]);
                aL[1] = __float_as_uint(ml[(rb + gid + 8) * P_STR + kk + tig]);
                aL[2] = __float_as_uint(ml[(rb + gid) * P_STR + kk + tig + 4]);
                aL[3] = __float_as_uint(ml[(rb + gid + 8) * P_STR + kk + tig + 4]);
                #pragma unroll
                for (int ni = 0; ni < 4; ni++)
                    MMA3(acc[mi][ni], aH, aL, bfH[ni], bfL[ni]);
            }
        }
        __syncthreads();
        cur ^= 1;
    }

    float d_store[4][4][4];
    #pragma unroll
    for (int mi = 0; mi < 4; mi++) {
        int rl0 = wm * 64 + mi * 16 + gid;
        float sr0 = g_sq[M0 + rl0], sr1 = g_sq[M0 + rl0 + 8];
        #pragma unroll
        for (int ni = 0; ni < 4; ni++) {
            int cl = wn * 32 + ni * 8 + tig * 2;
            float sc0 = g_sq[N0 + cl], sc1 = g_sq[N0 + cl + 1];
            float d00 = sr0 + sc0 - 2.f * acc[mi][ni][0];
            float d01 = sr0 + sc1 - 2.f * acc[mi][ni][1];
            float d10 = sr1 + sc0 - 2.f * acc[mi][ni][2];
            float d11 = sr1 + sc1 - 2.f * acc[mi][ni][3];
            if (mt == nt) {
                if (m0 + rl0 == n0 + cl)         d00 += 1e10f;
                if (m0 + rl0 == n0 + cl + 1)     d01 += 1e10f;
                if (m0 + rl0 + 8 == n0 + cl)     d10 += 1e10f;
                if (m0 + rl0 + 8 == n0 + cl + 1) d11 += 1e10f;
            }
            *(float2*)&g_gram[(size_t)(M0 + rl0) * NP + n0 + cl]     = make_float2(d00, d01);
            *(float2*)&g_gram[(size_t)(M0 + rl0 + 8) * NP + n0 + cl] = make_float2(d10, d11);
            d_store[mi][ni][0] = d00; d_store[mi][ni][1] = d01;
            d_store[mi][ni][2] = d10; d_store[mi][ni][3] = d11;
        }
    }

    if (mt != nt) {
        float* T = smem;
        __syncthreads();
        #pragma unroll
        for (int mi = 0; mi < 4; mi++) {
            int rl0 = wm * 64 + mi * 16 + gid;
            #pragma unroll
            for (int ni = 0; ni < 4; ni++) {
                int cl = wn * 32 + ni * 8 + tig * 2;
                T[(cl) * T_STR + rl0]         = d_store[mi][ni][0];
                T[(cl + 1) * T_STR + rl0]     = d_store[mi][ni][1];
                T[(cl) * T_STR + rl0 + 8]     = d_store[mi][ni][2];
                T[(cl + 1) * T_STR + rl0 + 8] = d_store[mi][ni][3];
            }
        }
        __syncthreads();
        for (int e = tid; e < 128 * 32; e += 256) {
            int r = e >> 5, q = (e & 31) * 4;
            *(float4*)&g_gram[(size_t)(N0 + r) * NP + m0 + q] =
                make_float4(T[r * T_STR + q], T[r * T_STR + q + 1],
                            T[r * T_STR + q + 2], T[r * T_STR + q + 3]);
        }
    }
}

// ---------------- kNN top-20: 2 rows per warp (interleaved REDUX chains) ----------------
__global__ __launch_bounds__(256) void k_knn() {
    int warp = (blockIdx.x * 256 + threadIdx.x) >> 5;
    int lane = threadIdx.x & 31;
    int wA = warp * 2, wB = wA + 1;
    if (wA >= BB * NP) return;
    const float* rowA = g_gram + (size_t)wA * NP;
    const float* rowB = g_gram + (size_t)wB * NP;

    unsigned kA[32], kB[32];
    #pragma unroll
    for (int jq = 0; jq < 8; jq++) {
        float4 a = *(const float4*)&rowA[lane * 4 + jq * 128];
        float4 b = *(const float4*)&rowB[lane * 4 + jq * 128];
        kA[jq*4+0] = ordkey(a.x); kA[jq*4+1] = ordkey(a.y);
        kA[jq*4+2] = ordkey(a.z); kA[jq*4+3] = ordkey(a.w);
        kB[jq*4+0] = ordkey(b.x); kB[jq*4+1] = ordkey(b.y);
        kB[jq*4+2] = ordkey(b.z); kB[jq*4+3] = ordkey(b.w);
    }
    #define COLOF(j) (unsigned)(lane * 4 + ((j) >> 2) * 128 + ((j) & 3))

    unsigned hA = 0xFFFFFFFFu, sA = 0xFFFFFFFFu; int hjA = 0, sjA = 0;
    unsigned hB = 0xFFFFFFFFu, sB = 0xFFFFFFFFu; int hjB = 0, sjB = 0;
    #pragma unroll
    for (int j = 0; j < 32; j++) {
        unsigned a = kA[j];
        if (a < hA)      { sA = hA; sjA = hjA; hA = a; hjA = j; }
        else if (a < sA) { sA = a; sjA = j; }
        unsigned b = kB[j];
        if (b < hB)      { sB = hB; sjB = hjB; hB = b; hjB = j; }
        else if (b < sB) { sB = b; sjB = j; }
    }

    unsigned usedA = 0u, usedB = 0u;
    int stA = 0, stB = 0;

    for (int t = 0; t < KNN; t++) {
        unsigned wminA = __reduce_min_sync(0xFFFFFFFFu, hA);
        unsigned wminB = __reduce_min_sync(0xFFFFFFFFu, hB);
        unsigned myA = (hA == wminA) ? COLOF(hjA) : 0xFFFFFFFFu;
        unsigned myB = (hB == wminB) ? COLOF(hjB) : 0xFFFFFFFFu;
        unsigned wiA = __reduce_min_sync(0xFFFFFFFFu, myA);
        unsigned wiB = __reduce_min_sync(0xFFFFFFFFu, myB);
        if (lane == 0) {
            g_idx[wA * KNN + t] = (int)wiA;
            g_idx[wB * KNN + t] = (int)wiB;
        }
        if (myA == wiA) {
            usedA |= 1u << hjA;
            stA++;
            if (stA == 1) { hA = sA; hjA = sjA; }
            else {
                hA = 0xFFFFFFFFu; hjA = 0;
                #pragma unroll
                for (int j = 0; j < 32; j++)
                    if (!((usedA >> j) & 1u) && kA[j] < hA) { hA = kA[j]; hjA = j; }
            }
        }
        if (myB == wiB) {
            usedB |= 1u << hjB;
            stB++;
            if (stB == 1) { hB = sB; hjB = sjB; }
            else {
                hB = 0xFFFFFFFFu; hjB = 0;
                #pragma unroll
                for (int j = 0; j < 32; j++)
                    if (!((usedB >> j) & 1u) && kB[j] < hB) { hB = kB[j]; hjB = j; }
            }
        }
    }
    #undef COLOF
}

// ---------------- split W into tf32 hi/lo planes ----------------
__global__ void k_splitW(const float* W, int K, int Kp, int cout) {
    int i = blockIdx.x * 256 + threadIdx.x;
    int N = 2 * cout;
    if (i >= Kp * N) return;
    int k = i / N, col = i % N;
    float v = 0.f;
    if (k < K) {
        if (col < cout) v = W[(size_t)k * cout + col];
        else {
            int c2 = col - cout;
            v = W[(size_t)(K + k) * cout + c2] - W[(size_t)k * cout + c2];
        }
    }
    float h = f2tf32f(v);
    g_wh[i] = h;
    g_wl[i] = f2tf32f(v - h);
}

// ---------------- 3xTF32 GEMM, pre-split operands, cp.async double-buffered ----------------
#define A_STR 20
#define B_STR 136
#define A_BUF (128*A_STR)
#define B_BUF (GBK*B_STR)
#define GEMM_SMEM ((2*A_BUF*2 + 2*B_BUF*2) * 4)   // 75776 bytes

__global__ __launch_bounds__(256) void k_gemm_tc(int M, int Kp, int N) {
    extern __shared__ float smem[];
    float* AsH = smem;
    float* AsL = AsH + 2 * A_BUF;
    float* BsH = AsL + 2 * A_BUF;
    float* BsL = BsH + 2 * B_BUF;

    uint32_t aH0 = (uint32_t)__cvta_generic_to_shared(AsH);
    uint32_t aL0 = (uint32_t)__cvta_generic_to_shared(AsL);
    uint32_t bH0 = (uint32_t)__cvta_generic_to_shared(BsH);
    uint32_t bL0 = (uint32_t)__cvta_generic_to_shared(BsL);

    int tid = threadIdx.x;
    int m0 = blockIdx.y * 128, n0 = blockIdx.x * 128;
    int wid = tid >> 5, lane = tid & 31;
    int wm = wid >> 2, wn = wid & 3;
    int gid = lane >> 2, tig = lane & 3;

    float acc[4][4][4];
    #pragma unroll
    for (int mi = 0; mi < 4; mi++)
        #pragma unroll
        for (int ni = 0; ni < 4; ni++)
            #pragma unroll
            for (int r = 0; r < 4; r++) acc[mi][ni][r] = 0.f;

    auto prefetch = [&](int buf, int k0) {
        #pragma unroll
        for (int i = 0; i < 2; i++) {
            int e = i * 256 + tid;
            int m = e >> 2, kq = e & 3;
            size_t src = (size_t)(m0 + m) * Kp + k0 + kq * 4;
            uint32_t d = (uint32_t)((buf * A_BUF + m * A_STR + kq * 4) * 4);
            cp16(aH0 + d, &g_ah[src]);
            cp16(aL0 + d, &g_al[src]);
        }
        #pragma unroll
        for (int i = 0; i < 2; i++) {
            int e = i * 256 + tid;
            int k = e >> 5, nq = e & 31;
            size_t src = (size_t)(k0 + k) * N + n0 + nq * 4;
            uint32_t d = (uint32_t)((buf * B_BUF + k * B_STR + nq * 4) * 4);
            cp16(bH0 + d, &g_wh[src]);
            cp16(bL0 + d, &g_wl[src]);
        }
        cp_commit();
    };

    int KT = Kp / GBK;
    prefetch(0, 0);

    int cur = 0;
    for (int kt = 0; kt < KT; kt++) {
        bool has_next = (kt + 1 < KT);
        if (has_next) prefetch(cur ^ 1, (kt + 1) * GBK);
        if (has_next) cp_wait1(); else cp_wait0();
        __syncthreads();

        const float* aH = AsH + cur * A_BUF;
        const float* aL = AsL + cur * A_BUF;
        const float* bH = BsH + cur * B_BUF;
        const float* bL = BsL + cur * B_BUF;

        #pragma unroll
        for (int kk = 0; kk < GBK; kk += 8) {
            unsigned bfH[4][2], bfL[4][2];
            #pragma unroll
            for (int ni = 0; ni < 4; ni++) {
                int cb = wn * 32 + ni * 8;
                bfH[ni][0] = __float_as_uint(bH[(kk + tig) * B_STR + cb + gid]);
                bfH[ni][1] = __float_as_uint(bH[(kk + tig + 4) * B_STR + cb + gid]);
                bfL[ni][0] = __float_as_uint(bL[(kk + tig) * B_STR + cb + gid]);
                bfL[ni][1] = __float_as_uint(bL[(kk + tig + 4) * B_STR + cb + gid]);
            }
            #pragma unroll
            for (int mi = 0; mi < 4; mi++) {
                int rb = wm * 64 + mi * 16;
                unsigned aHf[4], aLf[4];
                aHf[0] = __float_as_uint(aH[(rb + gid) * A_STR + kk + tig]);
                aHf[1] = __float_as_uint(aH[(rb + gid + 8) * A_STR + kk + tig]);
                aHf[2] = __float_as_uint(aH[(rb + gid) * A_STR + kk + tig + 4]);
                aHf[3] = __float_as_uint(aH[(rb + gid + 8) * A_STR + kk + tig + 4]);
                aLf[0] = __float_as_uint(aL[(rb + gid) * A_STR + kk + tig]);
                aLf[1] = __float_as_uint(aL[(rb + gid + 8) * A_STR + kk + tig]);
                aLf[2] = __float_as_uint(aL[(rb + gid) * A_STR + kk + tig + 4]);
                aLf[3] = __float_as_uint(aL[(rb + gid + 8) * A_STR + kk + tig + 4]);
                #pragma unroll
                for (int ni = 0; ni < 4; ni++)
                    MMA3(acc[mi][ni], aHf, aLf, bfH[ni], bfL[ni]);
            }
        }
        __syncthreads();
        cur ^= 1;
    }

    #pragma unroll
    for (int mi = 0; mi < 4; mi++) {
        int row0 = m0 + wm * 64 + mi * 16 + gid;
        #pragma unroll
        for (int ni = 0; ni < 4; ni++) {
            int col = n0 + wn * 32 + ni * 8 + tig * 2;
            *(float2*)&g_uv[(size_t)row0 * N + col]       = make_float2(acc[mi][ni][0], acc[mi][ni][1]);
            *(float2*)&g_uv[(size_t)(row0 + 8) * N + col] = make_float2(acc[mi][ni][2], acc[mi][ni][3]);
        }
    }
}

// ---------------- gather over k : max + stats; layer 4 fuses global pool ----------------
#define PTS 16
__global__ __launch_bounds__(256) void k_edge(int cout, int dopool) {
    __shared__ float ssum[1024], ssum2[1024];
    __shared__ int sidx[PTS * KNN];
    int tid = threadIdx.x;
    for (int i = tid; i < cout; i += 256) { ssum[i] = 0.f; ssum2[i] = 0.f; }

    int base = blockIdx.x * PTS;
    // stage all 16 points' indices once (320 ints)
    for (int i = tid; i < PTS * KNN; i += 256)
        sidx[i] = g_idx[(size_t)base * KNN + i];
    __syncthreads();

    int cpg = cout >> 2;
    int pp  = 256 / cpg;
    int pi = tid / cpg, ci = tid % cpg;
    int b = base / NP;
    int C2 = 2 * cout;
    int o = ci * 4;

    float4 se  = make_float4(0.f, 0.f, 0.f, 0.f);
    float4 se2 = make_float4(0.f, 0.f, 0.f, 0.f);
    float4 pm  = make_float4(-FLT_MAX, -FLT_MAX, -FLT_MAX, -FLT_MAX);

    for (int p0 = 0; p0 < PTS; p0 += pp) {
        int pl = p0 + pi;
        int bn = base + pl;
        int jj[KNN];
        #pragma unroll
        for (int k = 0; k < KNN; k++) jj[k] = sidx[pl * KNN + k];

        float4 u = *(const float4*)&g_uv[(size_t)bn * C2 + o];
        float4 mv = make_float4(-FLT_MAX, -FLT_MAX, -FLT_MAX, -FLT_MAX);
        #pragma unroll
        for (int k = 0; k < KNN; k++) {
            float4 v = *(const float4*)&g_uv[((size_t)b * NP + jj[k]) * C2 + cout + o];
            mv.x = fmaxf(mv.x, v.x); mv.y = fmaxf(mv.y, v.y);
            mv.z = fmaxf(mv.z, v.z); mv.w = fmaxf(mv.w, v.w);
            float4 e = make_float4(u.x + v.x, u.y + v.y, u.z + v.z, u.w + v.w);
            se.x += e.x; se.y += e.y; se.z += e.z; se.w += e.w;
            se2.x += e.x * e.x; se2.y += e.y * e.y; se2.z += e.z * e.z; se2.w += e.w * e.w;
        }
        float4 tot = make_float4(u.x + mv.x, u.y + mv.y, u.z + mv.z, u.w + mv.w);
        if (!dopool) {
            *(float4*)&g_u[(size_t)bn * cout + o] = tot;
        } else {
            pm.x = fmaxf(pm.x, tot.x); pm.y = fmaxf(pm.y, tot.y);
            pm.z = fmaxf(pm.z, tot.z); pm.w = fmaxf(pm.w, tot.w);
        }
    }

    if (dopool) {
        int* dst = &g_pool[b * 1024 + o];
        atomicMax(dst + 0, encf(pm.x));
        atomicMax(dst + 1, encf(pm.y));
        atomicMax(dst + 2, encf(pm.z));
        atomicMax(dst + 3, encf(pm.w));
    }

    atomicAdd(&ssum[o + 0], se.x);  atomicAdd(&ssum[o + 1], se.y);
    atomicAdd(&ssum[o + 2], se.z);  atomicAdd(&ssum[o + 3], se.w);
    atomicAdd(&ssum2[o + 0], se2.x); atomicAdd(&ssum2[o + 1], se2.y);
    atomicAdd(&ssum2[o + 2], se2.z); atomicAdd(&ssum2[o + 3], se2.w);
    __syncthreads();
    for (int i = tid; i < cout; i += 256) {
        atomicAdd(&g_sum[i],  ssum[i]);
        atomicAdd(&g_sum2[i], ssum2[i]);
    }
}

// ---------------- BN finalize (+ re-zero accumulators) ----------------
__global__ void k_fin(const float* gam, const float* bet, int cout) {
    int o = blockIdx.x * 256 + threadIdx.x;
    float s_ = g_sum[o], s2_ = g_sum2[o];
    g_sum[o] = 0.f;  g_sum2[o] = 0.f;
    if (o >= cout) return;
    float inv = 1.f / (float)EDGES;
    float mean = s_ * inv;
    float var  = s2_ * inv - mean * mean;
    float s = rsqrtf(var + 1e-5f) * gam[o];
    g_scale[o] = s;
    g_shift[o] = bet[o] - mean * s;
}

// ---------------- apply BN + relu, write next-layer planes + squared norms ----------------
__global__ void k_apply(int cout) {
    __shared__ float ssq[16];
    int tid = threadIdx.x;
    int ppb = 1024 / cout;
    if (tid < ppb) ssq[tid] = 0.f;
    __syncthreads();

    int i4 = (blockIdx.x * 256 + tid) * 4;
    int o = i4 & (cout - 1);
    int pl = tid / (cout >> 2);
    float4 u = *(const float4*)&g_u[i4];
    float4 s = *(const float4*)&g_scale[o];
    float4 t = *(const float4*)&g_shift[o];
    float4 v, h, l;
    v.x = fmaxf(u.x * s.x + t.x, 0.f);
    v.y = fmaxf(u.y * s.y + t.y, 0.f);
    v.z = fmaxf(u.z * s.z + t.z, 0.f);
    v.w = fmaxf(u.w * s.w + t.w, 0.f);
    h.x = f2tf32f(v.x); h.y = f2tf32f(v.y); h.z = f2tf32f(v.z); h.w = f2tf32f(v.w);
    l.x = f2tf32f(v.x - h.x); l.y = f2tf32f(v.y - h.y);
    l.z = f2tf32f(v.z - h.z); l.w = f2tf32f(v.w - h.w);
    *(float4*)&g_ah[i4] = h;
    *(float4*)&g_al[i4] = l;

    atomicAdd(&ssq[pl], v.x * v.x + v.y * v.y + v.z * v.z + v.w * v.w);
    __syncthreads();
    if (tid < ppb) g_sq[blockIdx.x * ppb + tid] = ssq[tid];
}

// ---------------- pool init (encoded -inf) + pooled BN finalize ----------------
__global__ void k_pzero() {
    int i = blockIdx.x * 256 + threadIdx.x;
    if (i < BB * 1024) g_pool[i] = (int)0x80000000;
}

__global__ void k_pfin() {
    int i = blockIdx.x * 256 + threadIdx.x;
    int o = i & 1023;
    float m = decf(g_pool[i]);
    float v = fmaxf(g_scale[o] * m + g_shift[o], 0.f);
    ((float*)g_pool)[i] = v;
}

// ---------------- FC layers ----------------
__global__ void k_fc1(const float* W, const float* bias) {
    int b = blockIdx.x, t = threadIdx.x;
    float a0 = bias[t], a1 = bias[t + 256];
    const float* y = (const float*)g_pool + b * 1024;
    #pragma unroll 4
    for (int c = 0; c < 1024; c++) {
        float xv = y[c];
        a0 += xv * W[c * 512 + t];
        a1 += xv * W[c * 512 + t + 256];
    }
    g_fc1[b * 512 + t]       = fmaxf(a0, 0.f);
    g_fc1[b * 512 + t + 256] = fmaxf(a1, 0.f);
}

__global__ void k_fc2(const float* W, const float* bias, float* out) {
    int b = blockIdx.x, o = threadIdx.x;
    if (o >= 40) return;
    float a = bias[o];
    const float* y = g_fc1 + b * 512;
    #pragma unroll 4
    for (int c = 0; c < 512; c++) a += y[c] * W[c * 40 + o];
    out[b * 40 + o] = a;
}

// ---------------- launcher (fork/join overlap: gram+knn || splitW+gemm) ----------------
extern "C" void kernel_launch(void* const* d_in, const int* in_sizes, int n_in,
                              void* d_out, int out_size) {
    (void)in_sizes; (void)n_in; (void)out_size;
    const float* pos = (const float*)d_in[0];
    const float* W[4]  = {(const float*)d_in[1],  (const float*)d_in[5],
                          (const float*)d_in[9],  (const float*)d_in[13]};
    const float* gm[4] = {(const float*)d_in[3],  (const float*)d_in[7],
                          (const float*)d_in[11], (const float*)d_in[15]};
    const float* bt[4] = {(const float*)d_in[4],  (const float*)d_in[8],
                          (const float*)d_in[12], (const float*)d_in[16]};
    const float* Wc1 = (const float*)d_in[17];
    const float* bc1 = (const float*)d_in[18];
    const float* Wc2 = (const float*)d_in[19];
    const float* bc2 = (const float*)d_in[20];

    const int cin[4]  = {3, 64, 64, 128};
    const int Kp[4]   = {16, 64, 64, 128};
    const int cout[4] = {64, 64, 128, 1024};
    const int M = BB * NP;

    static cudaStream_t s2 = nullptr;
    static cudaEvent_t evF[4], evJ[4];
    if (!s2) {
        cudaStreamCreateWithFlags(&s2, cudaStreamNonBlocking);
        for (int i = 0; i < 4; i++) {
            cudaEventCreateWithFlags(&evF[i], cudaEventDisableTiming);
            cudaEventCreateWithFlags(&evJ[i], cudaEventDisableTiming);
        }
        cudaFuncSetAttribute(k_gemm_tc, cudaFuncAttributeMaxDynamicSharedMemorySize, GEMM_SMEM);
        cudaFuncSetAttribute(k_gram_tc, cudaFuncAttributeMaxDynamicSharedMemorySize, GRAM_SMEM);
    }

    k_pzero<<<64, 256>>>();
    for (int l = 0; l < 4; l++) {
        int N2 = 2 * cout[l];
        if (l == 0) k_splitA<<<64, 256>>>(pos, cin[0], Kp[0]);

        // fork: activation planes ready on main stream
        cudaEventRecord(evF[l], 0);
        cudaStreamWaitEvent(s2, evF[l], 0);
        k_splitW<<<(Kp[l] * N2 + 255) / 256, 256, 0, s2>>>(W[l], cin[l], Kp[l], cout[l]);
        k_gemm_tc<<<dim3(N2 / 128, M / 128), 256, GEMM_SMEM, s2>>>(M, Kp[l], N2);
        cudaEventRecord(evJ[l], s2);

        // main: neighbor pipeline
        k_gram_tc<<<dim3(36, 1, BB), 256, GRAM_SMEM>>>(Kp[l]);
        k_knn<<<(M / 2 * 32) / 256, 256>>>();

        // join: edge needs gemm output + knn indices
        cudaStreamWaitEvent(0, evJ[l], 0);
        k_edge<<<M / PTS, 256>>>(cout[l], l == 3 ? 1 : 0);
        k_fin<<<4, 256>>>(gm[l], bt[l], cout[l]);
        if (l < 3) k_apply<<<(M * cout[l]) / 1024, 256>>>(cout[l]);
        else       k_pfin<<<64, 256>>>();
    }
    k_fc1<<<BB, 256>>>(Wc1, bc1);
    k_fc2<<<BB, 64>>>(Wc2, bc2, (float*)d_out);
}

// round 15
// speedup vs baseline: 2.1901x; 1.0445x over previous
#include <cuda_runtime.h>
#include <float.h>
#include <math.h>
#include <stdint.h>

#define BB 16
#define NP 1024
#define KNN 20
#define EDGES (BB*NP*KNN)

// ---------------- scratch ----------------
__device__ float g_gram[BB*NP*NP];
__device__ float g_uv[BB*NP*2048];        // [u | v], stride 2*cout
__device__ float g_u[BB*NP*1024];         // u + max_k v  (layers 1-3)
__device__ float g_ah[BB*NP*128];         // A hi plane [M][Kp]
__device__ float g_al[BB*NP*128];         // A lo plane
__device__ float g_wh[128*2048];          // W hi plane [Kp][N] (per layer)
__device__ float g_wl[128*2048];
__device__ float g_sq[BB*NP];
__device__ int   g_idx[BB*NP*KNN];
__device__ float g_sum[4096];             // per-layer BN sums (zeroed in k_pzero)
__device__ float g_sum2[4096];
__device__ int   g_pool[BB*1024];         // encoded raw max, then float after k_pfin
__device__ float g_fc1[BB*512];

__device__ __forceinline__ float f2tf32f(float f) {
    unsigned r;
    asm("cvt.rna.tf32.f32 %0, %1;" : "=r"(r) : "f"(f));
    return __uint_as_float(r);
}

__device__ __forceinline__ int encf(float f) {
    int i = __float_as_int(f);
    return i >= 0 ? i : (i ^ 0x7fffffff);
}
__device__ __forceinline__ float decf(int i) {
    return __int_as_float(i >= 0 ? i : (i ^ 0x7fffffff));
}
__device__ __forceinline__ unsigned ordkey(float f) {
    unsigned u = __float_as_uint(f);
    return (u & 0x80000000u) ? ~u : (u | 0x80000000u);
}

// cp.async helpers
__device__ __forceinline__ void cp16(uint32_t dst, const void* src) {
    asm volatile("cp.async.ca.shared.global [%0], [%1], 16;\n" :: "r"(dst), "l"(src));
}
__device__ __forceinline__ void cp_commit() { asm volatile("cp.async.commit_group;\n"); }
__device__ __forceinline__ void cp_wait1() { asm volatile("cp.async.wait_group 1;\n"); }
__device__ __forceinline__ void cp_wait0() { asm volatile("cp.async.wait_group 0;\n"); }

#define MMA3(ACC, AH, AL, BH, BL)                                                \
    do {                                                                         \
        asm volatile("mma.sync.aligned.m16n8k8.row.col.f32.tf32.tf32.f32 "       \
            "{%0,%1,%2,%3}, {%4,%5,%6,%7}, {%8,%9}, {%0,%1,%2,%3};"              \
            : "+f"(ACC[0]), "+f"(ACC[1]), "+f"(ACC[2]), "+f"(ACC[3])             \
            : "r"(AH[0]), "r"(AH[1]), "r"(AH[2]), "r"(AH[3]), "r"(BL[0]), "r"(BL[1])); \
        asm volatile("mma.sync.aligned.m16n8k8.row.col.f32.tf32.tf32.f32 "       \
            "{%0,%1,%2,%3}, {%4,%5,%6,%7}, {%8,%9}, {%0,%1,%2,%3};"              \
            : "+f"(ACC[0]), "+f"(ACC[1]), "+f"(ACC[2]), "+f"(ACC[3])             \
            : "r"(AL[0]), "r"(AL[1]), "r"(AL[2]), "r"(AL[3]), "r"(BH[0]), "r"(BH[1])); \
        asm volatile("mma.sync.aligned.m16n8k8.row.col.f32.tf32.tf32.f32 "       \
            "{%0,%1,%2,%3}, {%4,%5,%6,%7}, {%8,%9}, {%0,%1,%2,%3};"              \
            : "+f"(ACC[0]), "+f"(ACC[1]), "+f"(ACC[2]), "+f"(ACC[3])             \
            : "r"(AH[0]), "r"(AH[1]), "r"(AH[2]), "r"(AH[3]), "r"(BH[0]), "r"(BH[1])); \
    } while (0)

// ---------------- split layer-1 input (pos) into planes + squared norms ----------------
__global__ void k_splitA(const float* x, int K, int Kp) {
    int m = blockIdx.x * 256 + threadIdx.x;
    if (m >= BB * NP) return;
    float s = 0.f;
    for (int k = 0; k < Kp; k++) {
        float v = (k < K) ? x[(size_t)m * K + k] : 0.f;
        float h = f2tf32f(v);
        g_ah[(size_t)m * Kp + k] = h;
        g_al[(size_t)m * Kp + k] = f2tf32f(v - h);
        s += v * v;
    }
    g_sq[m] = s;
}

// ---------------- 3xTF32 Gram: symmetric, 36 tile pairs, tensor-core ----------------
#define GBK 16
#define P_STR 20
#define P_BUF (128*P_STR)
#define GRAM_SMEM (8 * P_BUF * 4)         // 81920 B
#define T_STR 132

__global__ __launch_bounds__(256) void k_gram_tc(int Kp) {
    extern __shared__ float smem[];
    float* MH = smem;
    float* ML = MH + 2 * P_BUF;
    float* NH = ML + 2 * P_BUF;
    float* NL = NH + 2 * P_BUF;

    uint32_t mh0 = (uint32_t)__cvta_generic_to_shared(MH);
    uint32_t ml0 = (uint32_t)__cvta_generic_to_shared(ML);
    uint32_t nh0 = (uint32_t)__cvta_generic_to_shared(NH);
    uint32_t nl0 = (uint32_t)__cvta_generic_to_shared(NL);

    int b = blockIdx.z;
    int p = blockIdx.x, mt = 0;
    while (p >= 8 - mt) { p -= 8 - mt; mt++; }
    int nt = mt + p;
    int m0 = mt * 128, n0 = nt * 128;
    int M0 = b * NP + m0, N0 = b * NP + n0;

    int tid = threadIdx.x;
    int wid = tid >> 5, lane = tid & 31;
    int wm = wid >> 2, wn = wid & 3;
    int gid = lane >> 2, tig = lane & 3;

    float acc[4][4][4];
    #pragma unroll
    for (int mi = 0; mi < 4; mi++)
        #pragma unroll
        for (int ni = 0; ni < 4; ni++)
            #pragma unroll
            for (int r = 0; r < 4; r++) acc[mi][ni][r] = 0.f;

    auto prefetch = [&](int buf, int k0) {
        #pragma unroll
        for (int i = 0; i < 2; i++) {
            int e = i * 256 + tid;
            int m = e >> 2, kq = e & 3;
            uint32_t d = (uint32_t)((buf * P_BUF + m * P_STR + kq * 4) * 4);
            size_t srm = (size_t)(M0 + m) * Kp + k0 + kq * 4;
            size_t srn = (size_t)(N0 + m) * Kp + k0 + kq * 4;
            cp16(mh0 + d, &g_ah[srm]);
            cp16(ml0 + d, &g_al[srm]);
            cp16(nh0 + d, &g_ah[srn]);
            cp16(nl0 + d, &g_al[srn]);
        }
        cp_commit();
    };

    int KT = Kp / GBK;
    prefetch(0, 0);

    int cur = 0;
    for (int kt = 0; kt < KT; kt++) {
        bool has_next = (kt + 1 < KT);
        if (has_next) prefetch(cur ^ 1, (kt + 1) * GBK);
        if (has_next) cp_wait1(); else cp_wait0();
        __syncthreads();

        const float* mh = MH + cur * P_BUF;
        const float* ml = ML + cur * P_BUF;
        const float* nh = NH + cur * P_BUF;
        const float* nl = NL + cur * P_BUF;

        #pragma unroll
        for (int kk = 0; kk < GBK; kk += 8) {
            unsigned bfH[4][2], bfL[4][2];
            #pragma unroll
            for (int ni = 0; ni < 4; ni++) {
                int cb = wn * 32 + ni * 8 + gid;
                bfH[ni][0] = __float_as_uint(nh[cb * P_STR + kk + tig]);
                bfH[ni][1] = __float_as_uint(nh[cb * P_STR + kk + tig + 4]);
                bfL[ni][0] = __float_as_uint(nl[cb * P_STR + kk + tig]);
                bfL[ni][1] = __float_as_uint(nl[cb * P_STR + kk + tig + 4]);
            }
            #pragma unroll
            for (int mi = 0; mi < 4; mi++) {
                int rb = wm * 64 + mi * 16;
                unsigned aH[4], aL[4];
                aH[0] = __float_as_uint(mh[(rb + gid) * P_STR + kk + tig]);
                aH[1] = __float_as_uint(mh[(rb + gid + 8) * P_STR + kk + tig]);
                aH[2] = __float_as_uint(mh[(rb + gid) * P_STR + kk + tig + 4]);
                aH[3] = __float_as_uint(mh[(rb + gid + 8) * P_STR + kk + tig + 4]);
                aL[0] = __float_as_uint(ml[(rb + gid) * P_STR + kk + tig]);
                aL[1] = __float_as_uint(ml[(rb + gid + 8) * P_STR + kk + tig]);
                aL[2] = __float_as_uint(ml[(rb + gid) * P_STR + kk + tig + 4]);
                aL[3] = __float_as_uint(ml[(rb + gid + 8) * P_STR + kk + tig + 4]);
                #pragma unroll
                for (int ni = 0; ni < 4; ni++)
                    MMA3(acc[mi][ni], aH, aL, bfH[ni], bfL[ni]);
            }
        }
        __syncthreads();
        cur ^= 1;
    }

    float d_store[4][4][4];
    #pragma unroll
    for (int mi = 0; mi < 4; mi++) {
        int rl0 = wm * 64 + mi * 16 + gid;
        float sr0 = g_sq[M0 + rl0], sr1 = g_sq[M0 + rl0 + 8];
        #pragma unroll
        for (int ni = 0; ni < 4; ni++) {
            int cl = wn * 32 + ni * 8 + tig * 2;
            float sc0 = g_sq[N0 + cl], sc1 = g_sq[N0 + cl + 1];
            float d00 = sr0 + sc0 - 2.f * acc[mi][ni][0];
            float d01 = sr0 + sc1 - 2.f * acc[mi][ni][1];
            float d10 = sr1 + sc0 - 2.f * acc[mi][ni][2];
            float d11 = sr1 + sc1 - 2.f * acc[mi][ni][3];
            if (mt == nt) {
                if (m0 + rl0 == n0 + cl)         d00 += 1e10f;
                if (m0 + rl0 == n0 + cl + 1)     d01 += 1e10f;
                if (m0 + rl0 + 8 == n0 + cl)     d10 += 1e10f;
                if (m0 + rl0 + 8 == n0 + cl + 1) d11 += 1e10f;
            }
            *(float2*)&g_gram[(size_t)(M0 + rl0) * NP + n0 + cl]     = make_float2(d00, d01);
            *(float2*)&g_gram[(size_t)(M0 + rl0 + 8) * NP + n0 + cl] = make_float2(d10, d11);
            d_store[mi][ni][0] = d00; d_store[mi][ni][1] = d01;
            d_store[mi][ni][2] = d10; d_store[mi][ni][3] = d11;
        }
    }

    if (mt != nt) {
        float* T = smem;
        __syncthreads();
        #pragma unroll
        for (int mi = 0; mi < 4; mi++) {
            int rl0 = wm * 64 + mi * 16 + gid;
            #pragma unroll
            for (int ni = 0; ni < 4; ni++) {
                int cl = wn * 32 + ni * 8 + tig * 2;
                T[(cl) * T_STR + rl0]         = d_store[mi][ni][0];
                T[(cl + 1) * T_STR + rl0]     = d_store[mi][ni][1];
                T[(cl) * T_STR + rl0 + 8]     = d_store[mi][ni][2];
                T[(cl + 1) * T_STR + rl0 + 8] = d_store[mi][ni][3];
            }
        }
        __syncthreads();
        for (int e = tid; e < 128 * 32; e += 256) {
            int r = e >> 5, q = (e & 31) * 4;
            *(float4*)&g_gram[(size_t)(N0 + r) * NP + m0 + q] =
                make_float4(T[r * T_STR + q], T[r * T_STR + q + 1],
                            T[r * T_STR + q + 2], T[r * T_STR + q + 3]);
        }
    }
}

// ---------------- kNN top-20: 2 rows per warp (interleaved REDUX chains) ----------------
__global__ __launch_bounds__(256) void k_knn() {
    int warp = (blockIdx.x * 256 + threadIdx.x) >> 5;
    int lane = threadIdx.x & 31;
    int wA = warp * 2, wB = wA + 1;
    if (wA >= BB * NP) return;
    const float* rowA = g_gram + (size_t)wA * NP;
    const float* rowB = g_gram + (size_t)wB * NP;

    unsigned kA[32], kB[32];
    #pragma unroll
    for (int jq = 0; jq < 8; jq++) {
        float4 a = *(const float4*)&rowA[lane * 4 + jq * 128];
        float4 b = *(const float4*)&rowB[lane * 4 + jq * 128];
        kA[jq*4+0] = ordkey(a.x); kA[jq*4+1] = ordkey(a.y);
        kA[jq*4+2] = ordkey(a.z); kA[jq*4+3] = ordkey(a.w);
        kB[jq*4+0] = ordkey(b.x); kB[jq*4+1] = ordkey(b.y);
        kB[jq*4+2] = ordkey(b.z); kB[jq*4+3] = ordkey(b.w);
    }
    #define COLOF(j) (unsigned)(lane * 4 + ((j) >> 2) * 128 + ((j) & 3))

    unsigned hA = 0xFFFFFFFFu, sA = 0xFFFFFFFFu; int hjA = 0, sjA = 0;
    unsigned hB = 0xFFFFFFFFu, sB = 0xFFFFFFFFu; int hjB = 0, sjB = 0;
    #pragma unroll
    for (int j = 0; j < 32; j++) {
        unsigned a = kA[j];
        if (a < hA)      { sA = hA; sjA = hjA; hA = a; hjA = j; }
        else if (a < sA) { sA = a; sjA = j; }
        unsigned b = kB[j];
        if (b < hB)      { sB = hB; sjB = hjB; hB = b; hjB = j; }
        else if (b < sB) { sB = b; sjB = j; }
    }

    unsigned usedA = 0u, usedB = 0u;
    int stA = 0, stB = 0;

    for (int t = 0; t < KNN; t++) {
        unsigned wminA = __reduce_min_sync(0xFFFFFFFFu, hA);
        unsigned wminB = __reduce_min_sync(0xFFFFFFFFu, hB);
        unsigned myA = (hA == wminA) ? COLOF(hjA) : 0xFFFFFFFFu;
        unsigned myB = (hB == wminB) ? COLOF(hjB) : 0xFFFFFFFFu;
        unsigned wiA = __reduce_min_sync(0xFFFFFFFFu, myA);
        unsigned wiB = __reduce_min_sync(0xFFFFFFFFu, myB);
        if (lane == 0) {
            g_idx[wA * KNN + t] = (int)wiA;
            g_idx[wB * KNN + t] = (int)wiB;
        }
        if (myA == wiA) {
            usedA |= 1u << hjA;
            stA++;
            if (stA == 1) { hA = sA; hjA = sjA; }
            else {
                hA = 0xFFFFFFFFu; hjA = 0;
                #pragma unroll
                for (int j = 0; j < 32; j++)
                    if (!((usedA >> j) & 1u) && kA[j] < hA) { hA = kA[j]; hjA = j; }
            }
        }
        if (myB == wiB) {
            usedB |= 1u << hjB;
            stB++;
            if (stB == 1) { hB = sB; hjB = sjB; }
            else {
                hB = 0xFFFFFFFFu; hjB = 0;
                #pragma unroll
                for (int j = 0; j < 32; j++)
                    if (!((usedB >> j) & 1u) && kB[j] < hB) { hB = kB[j]; hjB = j; }
            }
        }
    }
    #undef COLOF
}

// ---------------- split W into tf32 hi/lo planes ----------------
__global__ void k_splitW(const float* W, int K, int Kp, int cout) {
    int i = blockIdx.x * 256 + threadIdx.x;
    int N = 2 * cout;
    if (i >= Kp * N) return;
    int k = i / N, col = i % N;
    float v = 0.f;
    if (k < K) {
        if (col < cout) v = W[(size_t)k * cout + col];
        else {
            int c2 = col - cout;
            v = W[(size_t)(K + k) * cout + c2] - W[(size_t)k * cout + c2];
        }
    }
    float h = f2tf32f(v);
    g_wh[i] = h;
    g_wl[i] = f2tf32f(v - h);
}

// ---------------- 3xTF32 GEMM, 2 CTAs/SM, cp.async double-buffered ----------------
#define A_STR 20
#define B_STR 136
#define A_BUF (128*A_STR)
#define B_BUF (GBK*B_STR)
#define GEMM_SMEM ((2*A_BUF*2 + 2*B_BUF*2) * 4)   // 75776 bytes

__global__ __launch_bounds__(256, 2) void k_gemm_tc(int M, int Kp, int N) {
    extern __shared__ float smem[];
    float* AsH = smem;
    float* AsL = AsH + 2 * A_BUF;
    float* BsH = AsL + 2 * A_BUF;
    float* BsL = BsH + 2 * B_BUF;

    uint32_t aH0 = (uint32_t)__cvta_generic_to_shared(AsH);
    uint32_t aL0 = (uint32_t)__cvta_generic_to_shared(AsL);
    uint32_t bH0 = (uint32_t)__cvta_generic_to_shared(BsH);
    uint32_t bL0 = (uint32_t)__cvta_generic_to_shared(BsL);

    int tid = threadIdx.x;
    int m0 = blockIdx.y * 128, n0 = blockIdx.x * 128;
    int wid = tid >> 5, lane = tid & 31;
    int wm = wid >> 2, wn = wid & 3;
    int gid = lane >> 2, tig = lane & 3;

    float acc[4][4][4];
    #pragma unroll
    for (int mi = 0; mi < 4; mi++)
        #pragma unroll
        for (int ni = 0; ni < 4; ni++)
            #pragma unroll
            for (int r = 0; r < 4; r++) acc[mi][ni][r] = 0.f;

    auto prefetch = [&](int buf, int k0) {
        #pragma unroll
        for (int i = 0; i < 2; i++) {
            int e = i * 256 + tid;
            int m = e >> 2, kq = e & 3;
            size_t src = (size_t)(m0 + m) * Kp + k0 + kq * 4;
            uint32_t d = (uint32_t)((buf * A_BUF + m * A_STR + kq * 4) * 4);
            cp16(aH0 + d, &g_ah[src]);
            cp16(aL0 + d, &g_al[src]);
        }
        #pragma unroll
        for (int i = 0; i < 2; i++) {
            int e = i * 256 + tid;
            int k = e >> 5, nq = e & 31;
            size_t src = (size_t)(k0 + k) * N + n0 + nq * 4;
            uint32_t d = (uint32_t)((buf * B_BUF + k * B_STR + nq * 4) * 4);
            cp16(bH0 + d, &g_wh[src]);
            cp16(bL0 + d, &g_wl[src]);
        }
        cp_commit();
    };

    int KT = Kp / GBK;
    prefetch(0, 0);

    int cur = 0;
    for (int kt = 0; kt < KT; kt++) {
        bool has_next = (kt + 1 < KT);
        if (has_next) prefetch(cur ^ 1, (kt + 1) * GBK);
        if (has_next) cp_wait1(); else cp_wait0();
        __syncthreads();

        const float* aH = AsH + cur * A_BUF;
        const float* aL = AsL + cur * A_BUF;
        const float* bH = BsH + cur * B_BUF;
        const float* bL = BsL + cur * B_BUF;

        #pragma unroll
        for (int kk = 0; kk < GBK; kk += 8) {
            unsigned bfH[4][2], bfL[4][2];
            #pragma unroll
            for (int ni = 0; ni < 4; ni++) {
                int cb = wn * 32 + ni * 8;
                bfH[ni][0] = __float_as_uint(bH[(kk + tig) * B_STR + cb + gid]);
                bfH[ni][1] = __float_as_uint(bH[(kk + tig + 4) * B_STR + cb + gid]);
                bfL[ni][0] = __float_as_uint(bL[(kk + tig) * B_STR + cb + gid]);
                bfL[ni][1] = __float_as_uint(bL[(kk + tig + 4) * B_STR + cb + gid]);
            }
            #pragma unroll
            for (int mi = 0; mi < 4; mi++) {
                int rb = wm * 64 + mi * 16;
                unsigned aHf[4], aLf[4];
                aHf[0] = __float_as_uint(aH[(rb + gid) * A_STR + kk + tig]);
                aHf[1] = __float_as_uint(aH[(rb + gid + 8) * A_STR + kk + tig]);
                aHf[2] = __float_as_uint(aH[(rb + gid) * A_STR + kk + tig + 4]);
                aHf[3] = __float_as_uint(aH[(rb + gid + 8) * A_STR + kk + tig + 4]);
                aLf[0] = __float_as_uint(aL[(rb + gid) * A_STR + kk + tig]);
                aLf[1] = __float_as_uint(aL[(rb + gid + 8) * A_STR + kk + tig]);
                aLf[2] = __float_as_uint(aL[(rb + gid) * A_STR + kk + tig + 4]);
                aLf[3] = __float_as_uint(aL[(rb + gid + 8) * A_STR + kk + tig + 4]);
                #pragma unroll
                for (int ni = 0; ni < 4; ni++)
                    MMA3(acc[mi][ni], aHf, aLf, bfH[ni], bfL[ni]);
            }
        }
        __syncthreads();
        cur ^= 1;
    }

    #pragma unroll
    for (int mi = 0; mi < 4; mi++) {
        int row0 = m0 + wm * 64 + mi * 16 + gid;
        #pragma unroll
        for (int ni = 0; ni < 4; ni++) {
            int col = n0 + wn * 32 + ni * 8 + tig * 2;
            *(float2*)&g_uv[(size_t)row0 * N + col]       = make_float2(acc[mi][ni][0], acc[mi][ni][1]);
            *(float2*)&g_uv[(size_t)(row0 + 8) * N + col] = make_float2(acc[mi][ni][2], acc[mi][ni][3]);
        }
    }
}

// ---------------- gather over k : max + stats; layer 4 fuses global pool ----------------
#define PTS 16
__global__ __launch_bounds__(256) void k_edge(int cout, int dopool, int loff) {
    __shared__ float ssum[1024], ssum2[1024];
    __shared__ int sidx[PTS * KNN];
    int tid = threadIdx.x;
    for (int i = tid; i < cout; i += 256) { ssum[i] = 0.f; ssum2[i] = 0.f; }

    int base = blockIdx.x * PTS;
    for (int i = tid; i < PTS * KNN; i += 256)
        sidx[i] = g_idx[(size_t)base * KNN + i];
    __syncthreads();

    int cpg = cout >> 2;
    int pp  = 256 / cpg;
    int pi = tid / cpg, ci = tid % cpg;
    int b = base / NP;
    int C2 = 2 * cout;
    int o = ci * 4;

    float4 se  = make_float4(0.f, 0.f, 0.f, 0.f);
    float4 se2 = make_float4(0.f, 0.f, 0.f, 0.f);
    float4 pm  = make_float4(-FLT_MAX, -FLT_MAX, -FLT_MAX, -FLT_MAX);

    for (int p0 = 0; p0 < PTS; p0 += pp) {
        int pl = p0 + pi;
        int bn = base + pl;
        int jj[KNN];
        #pragma unroll
        for (int k = 0; k < KNN; k++) jj[k] = sidx[pl * KNN + k];

        float4 u = *(const float4*)&g_uv[(size_t)bn * C2 + o];
        float4 mv = make_float4(-FLT_MAX, -FLT_MAX, -FLT_MAX, -FLT_MAX);
        #pragma unroll
        for (int k = 0; k < KNN; k++) {
            float4 v = *(const float4*)&g_uv[((size_t)b * NP + jj[k]) * C2 + cout + o];
            mv.x = fmaxf(mv.x, v.x); mv.y = fmaxf(mv.y, v.y);
            mv.z = fmaxf(mv.z, v.z); mv.w = fmaxf(mv.w, v.w);
            float4 e = make_float4(u.x + v.x, u.y + v.y, u.z + v.z, u.w + v.w);
            se.x += e.x; se.y += e.y; se.z += e.z; se.w += e.w;
            se2.x += e.x * e.x; se2.y += e.y * e.y; se2.z += e.z * e.z; se2.w += e.w * e.w;
        }
        float4 tot = make_float4(u.x + mv.x, u.y + mv.y, u.z + mv.z, u.w + mv.w);
        if (!dopool) {
            *(float4*)&g_u[(size_t)bn * cout + o] = tot;
        } else {
            pm.x = fmaxf(pm.x, tot.x); pm.y = fmaxf(pm.y, tot.y);
            pm.z = fmaxf(pm.z, tot.z); pm.w = fmaxf(pm.w, tot.w);
        }
    }

    if (dopool) {
        int* dst = &g_pool[b * 1024 + o];
        atomicMax(dst + 0, encf(pm.x));
        atomicMax(dst + 1, encf(pm.y));
        atomicMax(dst + 2, encf(pm.z));
        atomicMax(dst + 3, encf(pm.w));
    }

    atomicAdd(&ssum[o + 0], se.x);  atomicAdd(&ssum[o + 1], se.y);
    atomicAdd(&ssum[o + 2], se.z);  atomicAdd(&ssum[o + 3], se.w);
    atomicAdd(&ssum2[o + 0], se2.x); atomicAdd(&ssum2[o + 1], se2.y);
    atomicAdd(&ssum2[o + 2], se2.z); atomicAdd(&ssum2[o + 3], se2.w);
    __syncthreads();
    for (int i = tid; i < cout; i += 256) {
        atomicAdd(&g_sum[loff + i],  ssum[i]);
        atomicAdd(&g_sum2[loff + i], ssum2[i]);
    }
}

// ---------------- apply BN + relu (scale/shift inline), write planes + sqnorms ----------------
__global__ void k_apply(int cout, int loff, const float* gam, const float* bet) {
    __shared__ float ssq[16];
    int tid = threadIdx.x;
    int ppb = 1024 / cout;
    if (tid < ppb) ssq[tid] = 0.f;
    __syncthreads();

    int i4 = (blockIdx.x * 256 + tid) * 4;
    int o = i4 & (cout - 1);
    int pl = tid / (cout >> 2);

    const float inv = 1.f / (float)EDGES;
    float sc[4], sh[4];
    #pragma unroll
    for (int j = 0; j < 4; j++) {
        float mean = g_sum[loff + o + j] * inv;
        float var  = g_sum2[loff + o + j] * inv - mean * mean;
        float s = rsqrtf(var + 1e-5f) * gam[o + j];
        sc[j] = s;
        sh[j] = bet[o + j] - mean * s;
    }

    float4 u = *(const float4*)&g_u[i4];
    float4 v, h, l;
    v.x = fmaxf(u.x * sc[0] + sh[0], 0.f);
    v.y = fmaxf(u.y * sc[1] + sh[1], 0.f);
    v.z = fmaxf(u.z * sc[2] + sh[2], 0.f);
    v.w = fmaxf(u.w * sc[3] + sh[3], 0.f);
    h.x = f2tf32f(v.x); h.y = f2tf32f(v.y); h.z = f2tf32f(v.z); h.w = f2tf32f(v.w);
    l.x = f2tf32f(v.x - h.x); l.y = f2tf32f(v.y - h.y);
    l.z = f2tf32f(v.z - h.z); l.w = f2tf32f(v.w - h.w);
    *(float4*)&g_ah[i4] = h;
    *(float4*)&g_al[i4] = l;

    atomicAdd(&ssq[pl], v.x * v.x + v.y * v.y + v.z * v.z + v.w * v.w);
    __syncthreads();
    if (tid < ppb) g_sq[blockIdx.x * ppb + tid] = ssq[tid];
}

// ---------------- pool init (encoded -inf + zero sums) + pooled BN finalize ----------------
__global__ void k_pzero() {
    int i = blockIdx.x * 256 + threadIdx.x;
    if (i < BB * 1024) g_pool[i] = (int)0x80000000;
    if (i < 4096) { g_sum[i] = 0.f; g_sum2[i] = 0.f; }
}

__global__ void k_pfin(const float* gam, const float* bet) {
    int i = blockIdx.x * 256 + threadIdx.x;
    int o = i & 1023;
    const float inv = 1.f / (float)EDGES;
    float mean = g_sum[3072 + o] * inv;
    float var  = g_sum2[3072 + o] * inv - mean * mean;
    float s = rsqrtf(var + 1e-5f) * gam[o];
    float t = bet[o] - mean * s;
    float m = decf(g_pool[i]);
    float v = fmaxf(s * m + t, 0.f);
    ((float*)g_pool)[i] = v;
}

// ---------------- FC layers ----------------
__global__ void k_fc1(const float* W, const float* bias) {
    int b = blockIdx.x, t = threadIdx.x;
    float a0 = bias[t], a1 = bias[t + 256];
    const float* y = (const float*)g_pool + b * 1024;
    #pragma unroll 4
    for (int c = 0; c < 1024; c++) {
        float xv = y[c];
        a0 += xv * W[c * 512 + t];
        a1 += xv * W[c * 512 + t + 256];
    }
    g_fc1[b * 512 + t]       = fmaxf(a0, 0.f);
    g_fc1[b * 512 + t + 256] = fmaxf(a1, 0.f);
}

__global__ void k_fc2(const float* W, const float* bias, float* out) {
    int b = blockIdx.x, o = threadIdx.x;
    if (o >= 40) return;
    float a = bias[o];
    const float* y = g_fc1 + b * 512;
    #pragma unroll 4
    for (int c = 0; c < 512; c++) a += y[c] * W[c * 40 + o];
    out[b * 40 + o] = a;
}

// ---------------- launcher (fork/join overlap: gram+knn || splitW+gemm) ----------------
extern "C" void kernel_launch(void* const* d_in, const int* in_sizes, int n_in,
                              void* d_out, int out_size) {
    (void)in_sizes; (void)n_in; (void)out_size;
    const float* pos = (const float*)d_in[0];
    const float* W[4]  = {(const float*)d_in[1],  (const float*)d_in[5],
                          (const float*)d_in[9],  (const float*)d_in[13]};
    const float* gm[4] = {(const float*)d_in[3],  (const float*)d_in[7],
                          (const float*)d_in[11], (const float*)d_in[15]};
    const float* bt[4] = {(const float*)d_in[4],  (const float*)d_in[8],
                          (const float*)d_in[12], (const float*)d_in[16]};
    const float* Wc1 = (const float*)d_in[17];
    const float* bc1 = (const float*)d_in[18];
    const float* Wc2 = (const float*)d_in[19];
    const float* bc2 = (const float*)d_in[20];

    const int cin[4]  = {3, 64, 64, 128};
    const int Kp[4]   = {16, 64, 64, 128};
    const int cout[4] = {64, 64, 128, 1024};
    const int M = BB * NP;

    static cudaStream_t s2 = nullptr;
    static cudaEvent_t evF[4], evJ[4];
    if (!s2) {
        cudaStreamCreateWithFlags(&s2, cudaStreamNonBlocking);
        for (int i = 0; i < 4; i++) {
            cudaEventCreateWithFlags(&evF[i], cudaEventDisableTiming);
            cudaEventCreateWithFlags(&evJ[i], cudaEventDisableTiming);
        }
        cudaFuncSetAttribute(k_gemm_tc, cudaFuncAttributeMaxDynamicSharedMemorySize, GEMM_SMEM);
        cudaFuncSetAttribute(k_gram_tc, cudaFuncAttributeMaxDynamicSharedMemorySize, GRAM_SMEM);
    }

    k_pzero<<<64, 256>>>();
    for (int l = 0; l < 4; l++) {
        int N2 = 2 * cout[l];
        if (l == 0) k_splitA<<<64, 256>>>(pos, cin[0], Kp[0]);

        // fork: activation planes ready on main stream
        cudaEventRecord(evF[l], 0);
        cudaStreamWaitEvent(s2, evF[l], 0);
        k_splitW<<<(Kp[l] * N2 + 255) / 256, 256, 0, s2>>>(W[l], cin[l], Kp[l], cout[l]);
        k_gemm_tc<<<dim3(N2 / 128, M / 128), 256, GEMM_SMEM, s2>>>(M, Kp[l], N2);
        cudaEventRecord(evJ[l], s2);

        // main: neighbor pipeline
        k_gram_tc<<<dim3(36, 1, BB), 256, GRAM_SMEM>>>(Kp[l]);
        k_knn<<<(M / 2 * 32) / 256, 256>>>();

        // join: edge needs gemm output + knn indices
        cudaStreamWaitEvent(0, evJ[l], 0);
        k_edge<<<M / PTS, 256>>>(cout[l], l == 3 ? 1 : 0, l * 1024);
        if (l < 3) k_apply<<<(M * cout[l]) / 1024, 256>>>(cout[l], l * 1024, gm[l], bt[l]);
        else       k_pfin<<<64, 256>>>(gm[3], bt[3]);
    }
    k_fc1<<<BB, 256>>>(Wc1, bc1);
    k_fc2<<<BB, 64>>>(Wc2, bc2, (float*)d_out);
}

// round 16
// speedup vs baseline: 2.1924x; 1.0011x over previous
#include <cuda_runtime.h>
#include <float.h>
#include <math.h>
#include <stdint.h>

#define BB 16
#define NP 1024
#define KNN 20
#define EDGES (BB*NP*KNN)

// ---------------- scratch ----------------
__device__ float g_gram[BB*NP*NP];        // distances, clamped >= 0 (raw-bit comparable)
__device__ float g_uv[BB*NP*2048];
__device__ float g_u[BB*NP*1024];
__device__ float g_ah[BB*NP*128];
__device__ float g_al[BB*NP*128];
__device__ float g_wh[128*2048];
__device__ float g_wl[128*2048];
__device__ float g_sq[BB*NP];
__device__ int   g_idx[BB*NP*KNN];
__device__ float g_sum[4096];
__device__ float g_sum2[4096];
__device__ int   g_pool[BB*1024];
__device__ float g_fc1[BB*512];

__device__ __forceinline__ float f2tf32f(float f) {
    unsigned r;
    asm("cvt.rna.tf32.f32 %0, %1;" : "=r"(r) : "f"(f));
    return __uint_as_float(r);
}
__device__ __forceinline__ int encf(float f) {
    int i = __float_as_int(f);
    return i >= 0 ? i : (i ^ 0x7fffffff);
}
__device__ __forceinline__ float decf(int i) {
    return __int_as_float(i >= 0 ? i : (i ^ 0x7fffffff));
}

// cp.async helpers
__device__ __forceinline__ void cp16(uint32_t dst, const void* src) {
    asm volatile("cp.async.ca.shared.global [%0], [%1], 16;\n" :: "r"(dst), "l"(src));
}
__device__ __forceinline__ void cp_commit() { asm volatile("cp.async.commit_group;\n"); }
__device__ __forceinline__ void cp_wait1() { asm volatile("cp.async.wait_group 1;\n"); }
__device__ __forceinline__ void cp_wait0() { asm volatile("cp.async.wait_group 0;\n"); }

#define MMA3(ACC, AH, AL, BH, BL)                                                \
    do {                                                                         \
        asm volatile("mma.sync.aligned.m16n8k8.row.col.f32.tf32.tf32.f32 "       \
            "{%0,%1,%2,%3}, {%4,%5,%6,%7}, {%8,%9}, {%0,%1,%2,%3};"              \
            : "+f"(ACC[0]), "+f"(ACC[1]), "+f"(ACC[2]), "+f"(ACC[3])             \
            : "r"(AH[0]), "r"(AH[1]), "r"(AH[2]), "r"(AH[3]), "r"(BL[0]), "r"(BL[1])); \
        asm volatile("mma.sync.aligned.m16n8k8.row.col.f32.tf32.tf32.f32 "       \
            "{%0,%1,%2,%3}, {%4,%5,%6,%7}, {%8,%9}, {%0,%1,%2,%3};"              \
            : "+f"(ACC[0]), "+f"(ACC[1]), "+f"(ACC[2]), "+f"(ACC[3])             \
            : "r"(AL[0]), "r"(AL[1]), "r"(AL[2]), "r"(AL[3]), "r"(BH[0]), "r"(BH[1])); \
        asm volatile("mma.sync.aligned.m16n8k8.row.col.f32.tf32.tf32.f32 "       \
            "{%0,%1,%2,%3}, {%4,%5,%6,%7}, {%8,%9}, {%0,%1,%2,%3};"              \
            : "+f"(ACC[0]), "+f"(ACC[1]), "+f"(ACC[2]), "+f"(ACC[3])             \
            : "r"(AH[0]), "r"(AH[1]), "r"(AH[2]), "r"(AH[3]), "r"(BH[0]), "r"(BH[1])); \
    } while (0)

// ---------------- split layer-1 input (pos) into planes + squared norms ----------------
__global__ void k_splitA(const float* x, int K, int Kp) {
    int m = blockIdx.x * 256 + threadIdx.x;
    if (m >= BB * NP) return;
    float s = 0.f;
    for (int k = 0; k < Kp; k++) {
        float v = (k < K) ? x[(size_t)m * K + k] : 0.f;
        float h = f2tf32f(v);
        g_ah[(size_t)m * Kp + k] = h;
        g_al[(size_t)m * Kp + k] = f2tf32f(v - h);
        s += v * v;
    }
    g_sq[m] = s;
}

// ---------------- 3xTF32 Gram: symmetric, 36 tile pairs, tensor-core ----------------
#define GBK 16
#define P_STR 20
#define P_BUF (128*P_STR)
#define GRAM_SMEM (8 * P_BUF * 4)         // 81920 B
#define T_STR 132

__global__ __launch_bounds__(256) void k_gram_tc(int Kp) {
    extern __shared__ float smem[];
    float* MH = smem;
    float* ML = MH + 2 * P_BUF;
    float* NH = ML + 2 * P_BUF;
    float* NL = NH + 2 * P_BUF;

    uint32_t mh0 = (uint32_t)__cvta_generic_to_shared(MH);
    uint32_t ml0 = (uint32_t)__cvta_generic_to_shared(ML);
    uint32_t nh0 = (uint32_t)__cvta_generic_to_shared(NH);
    uint32_t nl0 = (uint32_t)__cvta_generic_to_shared(NL);

    int b = blockIdx.z;
    int p = blockIdx.x, mt = 0;
    while (p >= 8 - mt) { p -= 8 - mt; mt++; }
    int nt = mt + p;
    int m0 = mt * 128, n0 = nt * 128;
    int M0 = b * NP + m0, N0 = b * NP + n0;

    int tid = threadIdx.x;
    int wid = tid >> 5, lane = tid & 31;
    int wm = wid >> 2, wn = wid & 3;
    int gid = lane >> 2, tig = lane & 3;

    float acc[4][4][4];
    #pragma unroll
    for (int mi = 0; mi < 4; mi++)
        #pragma unroll
        for (int ni = 0; ni < 4; ni++)
            #pragma unroll
            for (int r = 0; r < 4; r++) acc[mi][ni][r] = 0.f;

    auto prefetch = [&](int buf, int k0) {
        #pragma unroll
        for (int i = 0; i < 2; i++) {
            int e = i * 256 + tid;
            int m = e >> 2, kq = e & 3;
            uint32_t d = (uint32_t)((buf * P_BUF + m * P_STR + kq * 4) * 4);
            size_t srm = (size_t)(M0 + m) * Kp + k0 + kq * 4;
            size_t srn = (size_t)(N0 + m) * Kp + k0 + kq * 4;
            cp16(mh0 + d, &g_ah[srm]);
            cp16(ml0 + d, &g_al[srm]);
            cp16(nh0 + d, &g_ah[srn]);
            cp16(nl0 + d, &g_al[srn]);
        }
        cp_commit();
    };

    int KT = Kp / GBK;
    prefetch(0, 0);

    int cur = 0;
    for (int kt = 0; kt < KT; kt++) {
        bool has_next = (kt + 1 < KT);
        if (has_next) prefetch(cur ^ 1, (kt + 1) * GBK);
        if (has_next) cp_wait1(); else cp_wait0();
        __syncthreads();

        const float* mh = MH + cur * P_BUF;
        const float* ml = ML + cur * P_BUF;
        const float* nh = NH + cur * P_BUF;
        const float* nl = NL + cur * P_BUF;

        #pragma unroll
        for (int kk = 0; kk < GBK; kk += 8) {
            unsigned bfH[4][2], bfL[4][2];
            #pragma unroll
            for (int ni = 0; ni < 4; ni++) {
                int cb = wn * 32 + ni * 8 + gid;
                bfH[ni][0] = __float_as_uint(nh[cb * P_STR + kk + tig]);
                bfH[ni][1] = __float_as_uint(nh[cb * P_STR + kk + tig + 4]);
                bfL[ni][0] = __float_as_uint(nl[cb * P_STR + kk + tig]);
                bfL[ni][1] = __float_as_uint(nl[cb * P_STR + kk + tig + 4]);
            }
            #pragma unroll
            for (int mi = 0; mi < 4; mi++) {
                int rb = wm * 64 + mi * 16;
                unsigned aH[4], aL[4];
                aH[0] = __float_as_uint(mh[(rb + gid) * P_STR + kk + tig]);
                aH[1] = __float_as_uint(mh[(rb + gid + 8) * P_STR + kk + tig]);
                aH[2] = __float_as_uint(mh[(rb + gid) * P_STR + kk + tig + 4]);
                aH[3] = __float_as_uint(mh[(rb + gid + 8) * P_STR + kk + tig + 4]);
                aL[0] = __float_as_uint(ml[(rb + gid) * P_STR + kk + tig]);
                aL[1] = __float_as_uint(ml[(rb + gid + 8) * P_STR + kk + tig]);
                aL[2] = __float_as_uint(ml[(rb + gid) * P_STR + kk + tig + 4]);
                aL[3] = __float_as_uint(ml[(rb + gid + 8) * P_STR + kk + tig + 4]);
                #pragma unroll
                for (int ni = 0; ni < 4; ni++)
                    MMA3(acc[mi][ni], aH, aL, bfH[ni], bfL[ni]);
            }
        }
        __syncthreads();
        cur ^= 1;
    }

    float d_store[4][4][4];
    #pragma unroll
    for (int mi = 0; mi < 4; mi++) {
        int rl0 = wm * 64 + mi * 16 + gid;
        float sr0 = g_sq[M0 + rl0], sr1 = g_sq[M0 + rl0 + 8];
        #pragma unroll
        for (int ni = 0; ni < 4; ni++) {
            int cl = wn * 32 + ni * 8 + tig * 2;
            float sc0 = g_sq[N0 + cl], sc1 = g_sq[N0 + cl + 1];
            float d00 = sr0 + sc0 - 2.f * acc[mi][ni][0];
            float d01 = sr0 + sc1 - 2.f * acc[mi][ni][1];
            float d10 = sr1 + sc0 - 2.f * acc[mi][ni][2];
            float d11 = sr1 + sc1 - 2.f * acc[mi][ni][3];
            if (mt == nt) {
                if (m0 + rl0 == n0 + cl)         d00 += 1e10f;
                if (m0 + rl0 == n0 + cl + 1)     d01 += 1e10f;
                if (m0 + rl0 + 8 == n0 + cl)     d10 += 1e10f;
                if (m0 + rl0 + 8 == n0 + cl + 1) d11 += 1e10f;
            }
            d00 = fmaxf(d00, 0.f);   // clamp: non-negative floats compare as raw bits
            d01 = fmaxf(d01, 0.f);
            d10 = fmaxf(d10, 0.f);
            d11 = fmaxf(d11, 0.f);
            *(float2*)&g_gram[(size_t)(M0 + rl0) * NP + n0 + cl]     = make_float2(d00, d01);
            *(float2*)&g_gram[(size_t)(M0 + rl0 + 8) * NP + n0 + cl] = make_float2(d10, d11);
            d_store[mi][ni][0] = d00; d_store[mi][ni][1] = d01;
            d_store[mi][ni][2] = d10; d_store[mi][ni][3] = d11;
        }
    }

    if (mt != nt) {
        float* T = smem;
        __syncthreads();
        #pragma unroll
        for (int mi = 0; mi < 4; mi++) {
            int rl0 = wm * 64 + mi * 16 + gid;
            #pragma unroll
            for (int ni = 0; ni < 4; ni++) {
                int cl = wn * 32 + ni * 8 + tig * 2;
                T[(cl) * T_STR + rl0]         = d_store[mi][ni][0];
                T[(cl + 1) * T_STR + rl0]     = d_store[mi][ni][1];
                T[(cl) * T_STR + rl0 + 8]     = d_store[mi][ni][2];
                T[(cl + 1) * T_STR + rl0 + 8] = d_store[mi][ni][3];
            }
        }
        __syncthreads();
        for (int e = tid; e < 128 * 32; e += 256) {
            int r = e >> 5, q = (e & 31) * 4;
            *(float4*)&g_gram[(size_t)(N0 + r) * NP + m0 + q] =
                make_float4(T[r * T_STR + q], T[r * T_STR + q + 1],
                            T[r * T_STR + q + 2], T[r * T_STR + q + 3]);
        }
    }
}

// ---------------- kNN top-20: 2 rows/warp, tree-structured top-2 ----------------
__device__ __forceinline__ void top2merge(unsigned& hv, int& hj, unsigned& sv, int& sj,
                                          unsigned hv2, int hj2, unsigned sv2, int sj2) {
    // node1 indices all < node2 indices; strict < keeps lower index on ties
    if (hv2 < hv) {
        unsigned nsv = (sv2 < hv) ? sv2 : hv;
        int      nsj = (sv2 < hv) ? sj2 : hj;
        hv = hv2; hj = hj2;
        sv = nsv; sj = nsj;
    } else {
        if (hv2 < sv) { sv = hv2; sj = hj2; }
    }
}

__device__ __forceinline__ void top2tree(const unsigned* k,
                                         unsigned& h, int& hj, unsigned& s, int& sj) {
    unsigned hv[16], sv[16];
    int hjj[16], sjj[16];
    #pragma unroll
    for (int i = 0; i < 16; i++) {
        unsigned a = k[2 * i], b = k[2 * i + 1];
        bool lt = b < a;
        hv[i] = lt ? b : a;  hjj[i] = lt ? 2 * i + 1 : 2 * i;
        sv[i] = lt ? a : b;  sjj[i] = lt ? 2 * i : 2 * i + 1;
    }
    #pragma unroll
    for (int st = 8; st >= 1; st >>= 1)
        #pragma unroll
        for (int i = 0; i < st; i++)
            top2merge(hv[i], hjj[i], sv[i], sjj[i], hv[i + st], hjj[i + st], sv[i + st], sjj[i + st]);
    h = hv[0]; hj = hjj[0]; s = sv[0]; sj = sjj[0];
}

__global__ __launch_bounds__(256) void k_knn() {
    int warp = (blockIdx.x * 256 + threadIdx.x) >> 5;
    int lane = threadIdx.x & 31;
    int wA = warp * 2, wB = wA + 1;
    if (wA >= BB * NP) return;
    const unsigned* rowA = (const unsigned*)(g_gram + (size_t)wA * NP);
    const unsigned* rowB = (const unsigned*)(g_gram + (size_t)wB * NP);

    unsigned kA[32], kB[32];
    #pragma unroll
    for (int jq = 0; jq < 8; jq++) {
        uint4 a = *(const uint4*)&rowA[lane * 4 + jq * 128];
        uint4 b = *(const uint4*)&rowB[lane * 4 + jq * 128];
        kA[jq*4+0] = a.x; kA[jq*4+1] = a.y; kA[jq*4+2] = a.z; kA[jq*4+3] = a.w;
        kB[jq*4+0] = b.x; kB[jq*4+1] = b.y; kB[jq*4+2] = b.z; kB[jq*4+3] = b.w;
    }
    #define COLOF(j) (unsigned)(lane * 4 + ((j) >> 2) * 128 + ((j) & 3))

    unsigned hA, sA, hB, sB;
    int hjA, sjA, hjB, sjB;
    top2tree(kA, hA, hjA, sA, sjA);
    top2tree(kB, hB, hjB, sB, sjB);

    unsigned usedA = 0u, usedB = 0u;
    int stA = 0, stB = 0;

    for (int t = 0; t < KNN; t++) {
        unsigned wminA = __reduce_min_sync(0xFFFFFFFFu, hA);
        unsigned wminB = __reduce_min_sync(0xFFFFFFFFu, hB);
        unsigned myA = (hA == wminA) ? COLOF(hjA) : 0xFFFFFFFFu;
        unsigned myB = (hB == wminB) ? COLOF(hjB) : 0xFFFFFFFFu;
        unsigned wiA = __reduce_min_sync(0xFFFFFFFFu, myA);
        unsigned wiB = __reduce_min_sync(0xFFFFFFFFu, myB);
        if (lane == 0) {
            g_idx[wA * KNN + t] = (int)wiA;
            g_idx[wB * KNN + t] = (int)wiB;
        }
        if (myA == wiA) {
            usedA |= 1u << hjA;
            stA++;
            if (stA == 1) { hA = sA; hjA = sjA; }
            else {
                hA = 0xFFFFFFFFu; hjA = 0;
                #pragma unroll
                for (int j = 0; j < 32; j++)
                    if (!((usedA >> j) & 1u) && kA[j] < hA) { hA = kA[j]; hjA = j; }
            }
        }
        if (myB == wiB) {
            usedB |= 1u << hjB;
            stB++;
            if (stB == 1) { hB = sB; hjB = sjB; }
            else {
                hB = 0xFFFFFFFFu; hjB = 0;
                #pragma unroll
                for (int j = 0; j < 32; j++)
                    if (!((usedB >> j) & 1u) && kB[j] < hB) { hB = kB[j]; hjB = j; }
            }
        }
    }
    #undef COLOF
}

// ---------------- split W into tf32 hi/lo planes ----------------
__global__ void k_splitW(const float* W, int K, int Kp, int cout) {
    int i = blockIdx.x * 256 + threadIdx.x;
    int N = 2 * cout;
    if (i >= Kp * N) return;
    int k = i / N, col = i % N;
    float v = 0.f;
    if (k < K) {
        if (col < cout) v = W[(size_t)k * cout + col];
        else {
            int c2 = col - cout;
            v = W[(size_t)(K + k) * cout + c2] - W[(size_t)k * cout + c2];
        }
    }
    float h = f2tf32f(v);
    g_wh[i] = h;
    g_wl[i] = f2tf32f(v - h);
}

// ---------------- 3xTF32 GEMM, 2 CTAs/SM, cp.async double-buffered ----------------
#define A_STR 20
#define B_STR 136
#define A_BUF (128*A_STR)
#define B_BUF (GBK*B_STR)
#define GEMM_SMEM ((2*A_BUF*2 + 2*B_BUF*2) * 4)   // 75776 bytes

__global__ __launch_bounds__(256, 2) void k_gemm_tc(int M, int Kp, int N) {
    extern __shared__ float smem[];
    float* AsH = smem;
    float* AsL = AsH + 2 * A_BUF;
    float* BsH = AsL + 2 * A_BUF;
    float* BsL = BsH + 2 * B_BUF;

    uint32_t aH0 = (uint32_t)__cvta_generic_to_shared(AsH);
    uint32_t aL0 = (uint32_t)__cvta_generic_to_shared(AsL);
    uint32_t bH0 = (uint32_t)__cvta_generic_to_shared(BsH);
    uint32_t bL0 = (uint32_t)__cvta_generic_to_shared(BsL);

    int tid = threadIdx.x;
    int m0 = blockIdx.y * 128, n0 = blockIdx.x * 128;
    int wid = tid >> 5, lane = tid & 31;
    int wm = wid >> 2, wn = wid & 3;
    int gid = lane >> 2, tig = lane & 3;

    float acc[4][4][4];
    #pragma unroll
    for (int mi = 0; mi < 4; mi++)
        #pragma unroll
        for (int ni = 0; ni < 4; ni++)
            #pragma unroll
            for (int r = 0; r < 4; r++) acc[mi][ni][r] = 0.f;

    auto prefetch = [&](int buf, int k0) {
        #pragma unroll
        for (int i = 0; i < 2; i++) {
            int e = i * 256 + tid;
            int m = e >> 2, kq = e & 3;
            size_t src = (size_t)(m0 + m) * Kp + k0 + kq * 4;
            uint32_t d = (uint32_t)((buf * A_BUF + m * A_STR + kq * 4) * 4);
            cp16(aH0 + d, &g_ah[src]);
            cp16(aL0 + d, &g_al[src]);
        }
        #pragma unroll
        for (int i = 0; i < 2; i++) {
            int e = i * 256 + tid;
            int k = e >> 5, nq = e & 31;
            size_t src = (size_t)(k0 + k) * N + n0 + nq * 4;
            uint32_t d = (uint32_t)((buf * B_BUF + k * B_STR + nq * 4) * 4);
            cp16(bH0 + d, &g_wh[src]);
            cp16(bL0 + d, &g_wl[src]);
        }
        cp_commit();
    };

    int KT = Kp / GBK;
    prefetch(0, 0);

    int cur = 0;
    for (int kt = 0; kt < KT; kt++) {
        bool has_next = (kt + 1 < KT);
        if (has_next) prefetch(cur ^ 1, (kt + 1) * GBK);
        if (has_next) cp_wait1(); else cp_wait0();
        __syncthreads();

        const float* aH = AsH + cur * A_BUF;
        const float* aL = AsL + cur * A_BUF;
        const float* bH = BsH + cur * B_BUF;
        const float* bL = BsL + cur * B_BUF;

        #pragma unroll
        for (int kk = 0; kk < GBK; kk += 8) {
            unsigned bfH[4][2], bfL[4][2];
            #pragma unroll
            for (int ni = 0; ni < 4; ni++) {
                int cb = wn * 32 + ni * 8;
                bfH[ni][0] = __float_as_uint(bH[(kk + tig) * B_STR + cb + gid]);
                bfH[ni][1] = __float_as_uint(bH[(kk + tig + 4) * B_STR + cb + gid]);
                bfL[ni][0] = __float_as_uint(bL[(kk + tig) * B_STR + cb + gid]);
                bfL[ni][1] = __float_as_uint(bL[(kk + tig + 4) * B_STR + cb + gid]);
            }
            #pragma unroll
            for (int mi = 0; mi < 4; mi++) {
                int rb = wm * 64 + mi * 16;
                unsigned aHf[4], aLf[4];
                aHf[0] = __float_as_uint(aH[(rb + gid) * A_STR + kk + tig]);
                aHf[1] = __float_as_uint(aH[(rb + gid + 8) * A_STR + kk + tig]);
                aHf[2] = __float_as_uint(aH[(rb + gid) * A_STR + kk + tig + 4]);
                aHf[3] = __float_as_uint(aH[(rb + gid + 8) * A_STR + kk + tig + 4]);
                aLf[0] = __float_as_uint(aL[(rb + gid) * A_STR + kk + tig]);
                aLf[1] = __float_as_uint(aL[(rb + gid + 8) * A_STR + kk + tig]);
                aLf[2] = __float_as_uint(aL[(rb + gid) * A_STR + kk + tig + 4]);
                aLf[3] = __float_as_uint(aL[(rb + gid + 8) * A_STR + kk + tig + 4]);
                #pragma unroll
                for (int ni = 0; ni < 4; ni++)
                    MMA3(acc[mi][ni], aHf, aLf, bfH[ni], bfL[ni]);
            }
        }
        __syncthreads();
        cur ^= 1;
    }

    #pragma unroll
    for (int mi = 0; mi < 4; mi++) {
        int row0 = m0 + wm * 64 + mi * 16 + gid;
        #pragma unroll
        for (int ni = 0; ni < 4; ni++) {
            int col = n0 + wn * 32 + ni * 8 + tig * 2;
            *(float2*)&g_uv[(size_t)row0 * N + col]       = make_float2(acc[mi][ni][0], acc[mi][ni][1]);
            *(float2*)&g_uv[(size_t)(row0 + 8) * N + col] = make_float2(acc[mi][ni][2], acc[mi][ni][3]);
        }
    }
}

// ---------------- gather over k : max + stats; layer 4 fuses global pool ----------------
#define PTS 16
__global__ __launch_bounds__(256) void k_edge(int cout, int dopool, int loff) {
    __shared__ float ssum[1024], ssum2[1024];
    __shared__ int sidx[PTS * KNN];
    int tid = threadIdx.x;
    for (int i = tid; i < cout; i += 256) { ssum[i] = 0.f; ssum2[i] = 0.f; }

    int base = blockIdx.x * PTS;
    for (int i = tid; i < PTS * KNN; i += 256)
        sidx[i] = g_idx[(size_t)base * KNN + i];
    __syncthreads();

    int cpg = cout >> 2;
    int pp  = 256 / cpg;
    int pi = tid / cpg, ci = tid % cpg;
    int b = base / NP;
    int C2 = 2 * cout;
    int o = ci * 4;

    float4 se  = make_float4(0.f, 0.f, 0.f, 0.f);
    float4 se2 = make_float4(0.f, 0.f, 0.f, 0.f);
    float4 pm  = make_float4(-FLT_MAX, -FLT_MAX, -FLT_MAX, -FLT_MAX);

    for (int p0 = 0; p0 < PTS; p0 += pp) {
        int pl = p0 + pi;
        int bn = base + pl;
        int jj[KNN];
        #pragma unroll
        for (int k = 0; k < KNN; k++) jj[k] = sidx[pl * KNN + k];

        float4 u = *(const float4*)&g_uv[(size_t)bn * C2 + o];
        float4 mv = make_float4(-FLT_MAX, -FLT_MAX, -FLT_MAX, -FLT_MAX);
        #pragma unroll
        for (int k = 0; k < KNN; k++) {
            float4 v = *(const float4*)&g_uv[((size_t)b * NP + jj[k]) * C2 + cout + o];
            mv.x = fmaxf(mv.x, v.x); mv.y = fmaxf(mv.y, v.y);
            mv.z = fmaxf(mv.z, v.z); mv.w = fmaxf(mv.w, v.w);
            float4 e = make_float4(u.x + v.x, u.y + v.y, u.z + v.z, u.w + v.w);
            se.x += e.x; se.y += e.y; se.z += e.z; se.w += e.w;
            se2.x += e.x * e.x; se2.y += e.y * e.y; se2.z += e.z * e.z; se2.w += e.w * e.w;
        }
        float4 tot = make_float4(u.x + mv.x, u.y + mv.y, u.z + mv.z, u.w + mv.w);
        if (!dopool) {
            *(float4*)&g_u[(size_t)bn * cout + o] = tot;
        } else {
            pm.x = fmaxf(pm.x, tot.x); pm.y = fmaxf(pm.y, tot.y);
            pm.z = fmaxf(pm.z, tot.z); pm.w = fmaxf(pm.w, tot.w);
        }
    }

    if (dopool) {
        int* dst = &g_pool[b * 1024 + o];
        atomicMax(dst + 0, encf(pm.x));
        atomicMax(dst + 1, encf(pm.y));
        atomicMax(dst + 2, encf(pm.z));
        atomicMax(dst + 3, encf(pm.w));
    }

    atomicAdd(&ssum[o + 0], se.x);  atomicAdd(&ssum[o + 1], se.y);
    atomicAdd(&ssum[o + 2], se.z);  atomicAdd(&ssum[o + 3], se.w);
    atomicAdd(&ssum2[o + 0], se2.x); atomicAdd(&ssum2[o + 1], se2.y);
    atomicAdd(&ssum2[o + 2], se2.z); atomicAdd(&ssum2[o + 3], se2.w);
    __syncthreads();
    for (int i = tid; i < cout; i += 256) {
        atomicAdd(&g_sum[loff + i],  ssum[i]);
        atomicAdd(&g_sum2[loff + i], ssum2[i]);
    }
}

// ---------------- apply BN + relu (scale/shift inline), write planes + sqnorms ----------------
__global__ void k_apply(int cout, int loff, const float* gam, const float* bet) {
    __shared__ float ssq[16];
    int tid = threadIdx.x;
    int ppb = 1024 / cout;
    if (tid < ppb) ssq[tid] = 0.f;
    __syncthreads();

    int i4 = (blockIdx.x * 256 + tid) * 4;
    int o = i4 & (cout - 1);
    int pl = tid / (cout >> 2);

    const float inv = 1.f / (float)EDGES;
    float sc[4], sh[4];
    #pragma unroll
    for (int j = 0; j < 4; j++) {
        float mean = g_sum[loff + o + j] * inv;
        float var  = g_sum2[loff + o + j] * inv - mean * mean;
        float s = rsqrtf(var + 1e-5f) * gam[o + j];
        sc[j] = s;
        sh[j] = bet[o + j] - mean * s;
    }

    float4 u = *(const float4*)&g_u[i4];
    float4 v, h, l;
    v.x = fmaxf(u.x * sc[0] + sh[0], 0.f);
    v.y = fmaxf(u.y * sc[1] + sh[1], 0.f);
    v.z = fmaxf(u.z * sc[2] + sh[2], 0.f);
    v.w = fmaxf(u.w * sc[3] + sh[3], 0.f);
    h.x = f2tf32f(v.x); h.y = f2tf32f(v.y); h.z = f2tf32f(v.z); h.w = f2tf32f(v.w);
    l.x = f2tf32f(v.x - h.x); l.y = f2tf32f(v.y - h.y);
    l.z = f2tf32f(v.z - h.z); l.w = f2tf32f(v.w - h.w);
    *(float4*)&g_ah[i4] = h;
    *(float4*)&g_al[i4] = l;

    atomicAdd(&ssq[pl], v.x * v.x + v.y * v.y + v.z * v.z + v.w * v.w);
    __syncthreads();
    if (tid < ppb) g_sq[blockIdx.x * ppb + tid] = ssq[tid];
}

// ---------------- pool init (encoded -inf + zero sums) + pooled BN finalize ----------------
__global__ void k_pzero() {
    int i = blockIdx.x * 256 + threadIdx.x;
    if (i < BB * 1024) g_pool[i] = (int)0x80000000;
    if (i < 4096) { g_sum[i] = 0.f; g_sum2[i] = 0.f; }
}

__global__ void k_pfin(const float* gam, const float* bet) {
    int i = blockIdx.x * 256 + threadIdx.x;
    int o = i & 1023;
    const float inv = 1.f / (float)EDGES;
    float mean = g_sum[3072 + o] * inv;
    float var  = g_sum2[3072 + o] * inv - mean * mean;
    float s = rsqrtf(var + 1e-5f) * gam[o];
    float t = bet[o] - mean * s;
    float m = decf(g_pool[i]);
    float v = fmaxf(s * m + t, 0.f);
    ((float*)g_pool)[i] = v;
}

// ---------------- FC layers ----------------
__global__ void k_fc1(const float* W, const float* bias) {
    int b = blockIdx.x, t = threadIdx.x;
    float a0 = bias[t], a1 = bias[t + 256];
    const float* y = (const float*)g_pool + b * 1024;
    #pragma unroll 4
    for (int c = 0; c < 1024; c++) {
        float xv = y[c];
        a0 += xv * W[c * 512 + t];
        a1 += xv * W[c * 512 + t + 256];
    }
    g_fc1[b * 512 + t]       = fmaxf(a0, 0.f);
    g_fc1[b * 512 + t + 256] = fmaxf(a1, 0.f);
}

__global__ void k_fc2(const float* W, const float* bias, float* out) {
    int b = blockIdx.x, o = threadIdx.x;
    if (o >= 40) return;
    float a = bias[o];
    const float* y = g_fc1 + b * 512;
    #pragma unroll 4
    for (int c = 0; c < 512; c++) a += y[c] * W[c * 40 + o];
    out[b * 40 + o] = a;
}

// ---------------- launcher (fork/join overlap: gram+knn || splitW+gemm) ----------------
extern "C" void kernel_launch(void* const* d_in, const int* in_sizes, int n_in,
                              void* d_out, int out_size) {
    (void)in_sizes; (void)n_in; (void)out_size;
    const float* pos = (const float*)d_in[0];
    const float* W[4]  = {(const float*)d_in[1],  (const float*)d_in[5],
                          (const float*)d_in[9],  (const float*)d_in[13]};
    const float* gm[4] = {(const float*)d_in[3],  (const float*)d_in[7],
                          (const float*)d_in[11], (const float*)d_in[15]};
    const float* bt[4] = {(const float*)d_in[4],  (const float*)d_in[8],
                          (const float*)d_in[12], (const float*)d_in[16]};
    const float* Wc1 = (const float*)d_in[17];
    const float* bc1 = (const float*)d_in[18];
    const float* Wc2 = (const float*)d_in[19];
    const float* bc2 = (const float*)d_in[20];

    const int cin[4]  = {3, 64, 64, 128};
    const int Kp[4]   = {16, 64, 64, 128};
    const int cout[4] = {64, 64, 128, 1024};
    const int M = BB * NP;

    static cudaStream_t s2 = nullptr;
    static cudaEvent_t evF[4], evJ[4];
    if (!s2) {
        cudaStreamCreateWithFlags(&s2, cudaStreamNonBlocking);
        for (int i = 0; i < 4; i++) {
            cudaEventCreateWithFlags(&evF[i], cudaEventDisableTiming);
            cudaEventCreateWithFlags(&evJ[i], cudaEventDisableTiming);
        }
        cudaFuncSetAttribute(k_gemm_tc, cudaFuncAttributeMaxDynamicSharedMemorySize, GEMM_SMEM);
        cudaFuncSetAttribute(k_gram_tc, cudaFuncAttributeMaxDynamicSharedMemorySize, GRAM_SMEM);
    }

    k_pzero<<<64, 256>>>();
    for (int l = 0; l < 4; l++) {
        int N2 = 2 * cout[l];
        if (l == 0) k_splitA<<<64, 256>>>(pos, cin[0], Kp[0]);

        // fork: activation planes ready on main stream
        cudaEventRecord(evF[l], 0);
        cudaStreamWaitEvent(s2, evF[l], 0);
        k_splitW<<<(Kp[l] * N2 + 255) / 256, 256, 0, s2>>>(W[l], cin[l], Kp[l], cout[l]);
        k_gemm_tc<<<dim3(N2 / 128, M / 128), 256, GEMM_SMEM, s2>>>(M, Kp[l], N2);
        cudaEventRecord(evJ[l], s2);

        // main: neighbor pipeline
        k_gram_tc<<<dim3(36, 1, BB), 256, GRAM_SMEM>>>(Kp[l]);
        k_knn<<<(M / 2 * 32) / 256, 256>>>();

        // join: edge needs gemm output + knn indices
        cudaStreamWaitEvent(0, evJ[l], 0);
        k_edge<<<M / PTS, 256>>>(cout[l], l == 3 ? 1 : 0, l * 1024);
        if (l < 3) k_apply<<<(M * cout[l]) / 1024, 256>>>(cout[l], l * 1024, gm[l], bt[l]);
        else       k_pfin<<<64, 256>>>(gm[3], bt[3]);
    }
    k_fc1<<<BB, 256>>>(Wc1, bc1);
    k_fc2<<<BB, 64>>>(Wc2, bc2, (float*)d_out);
}